// round 8
// baseline (speedup 1.0000x reference)
#include <cuda_runtime.h>
#include <math.h>
#include <stdint.h>

#define Bn   32
#define Tn   24
#define Cn   512
#define Nn   (Bn*Cn)          // 16384
#define INF  14
#define HIDn 36
#define FFNn 144
#define HDn  18
#define EG   8192
#define SEQ  2
#define Rn   (SEQ*Tn)         // 48 rows per CTA
#define NT   128

// ---------------- scratch (device globals) -----------------------------------
__device__ float d_xn [Nn*Tn*INF];   // first-half features, [N][T][14] (t*14+f)
__device__ float d_xn2[Nn*Tn*INF];   // second-half features
__device__ int   d_deg[Cn];
__device__ int   d_colcnt[Cn];
__device__ int   d_off[Cn+1];
__device__ float d_dinv[Cn];
__device__ int   d_brow[EG];
__device__ float d_bw[EG];
__device__ float d_pe[HIDn*Tn];      // PE table, layout [o][t]

// ---------------- K1: per-node degree (rows) and col counts ------------------
__global__ void k_count(const int* __restrict__ ei) {
    int c = blockIdx.x, lane = threadIdx.x;
    int cr = 0, cc = 0;
    for (int e = lane; e < EG; e += 32) {
        cr += (ei[e]      == c);
        cc += (ei[EG + e] == c);
    }
    #pragma unroll
    for (int o = 16; o; o >>= 1) {
        cr += __shfl_down_sync(0xffffffffu, cr, o);
        cc += __shfl_down_sync(0xffffffffu, cc, o);
    }
    if (lane == 0) { d_deg[c] = cr; d_colcnt[c] = cc; }
}

// ---------------- K2: scan col counts -> CSR offsets; dinv; PE table ----------
__global__ void k_scan() {
    __shared__ int s[Cn];
    int t = threadIdx.x;
    s[t] = d_colcnt[t];
    __syncthreads();
    for (int o = 1; o < Cn; o <<= 1) {
        int v = (t >= o) ? s[t - o] : 0;
        __syncthreads();
        s[t] += v;
        __syncthreads();
    }
    d_off[t + 1] = s[t];
    if (t == 0) d_off[0] = 0;
    int dg = d_deg[t];
    d_dinv[t] = (dg > 0) ? (1.0f / sqrtf((float)dg)) : 0.0f;
    // PE table: d_pe[o*Tn + tt] = sin/cos(tt * exp(-ln(10000)*(o&~1)/36))
    for (int i = t; i < HIDn * Tn; i += Cn) {
        int o = i / Tn, tt = i % Tn;
        float div = expf(-9.210340371976184f * (float)(o & ~1) / (float)HIDn);
        float ang = (float)tt * div;
        d_pe[i] = (o & 1) ? cosf(ang) : sinf(ang);
    }
}

// ---------------- K3: fill CSR buckets, stable in edge order ------------------
__global__ void k_fill(const int* __restrict__ ei) {
    int c = blockIdx.x, lane = threadIdx.x;
    int base = d_off[c];
    float dc = d_dinv[c];
    for (int e0 = 0; e0 < EG; e0 += 32) {
        int e = e0 + lane;
        int col = ei[EG + e];
        bool m = (col == c);
        unsigned mask = __ballot_sync(0xffffffffu, m);
        if (m) {
            int pos = base + __popc(mask & ((1u << lane) - 1u));
            int r = ei[e];
            d_brow[pos] = r;
            d_bw[pos]   = -(d_dinv[r] * dc);
        }
        base += __popc(mask);
    }
}

// ---------------- K4: pack xn / xn2 into [N][T][14] ---------------------------
__global__ void k_pack(const float* __restrict__ pm, const float* __restrict__ ft) {
    int idx = blockIdx.x * blockDim.x + threadIdx.x;
    if (idx >= Nn * Tn * INF) return;
    int f  = idx % INF;
    int rt = idx / INF;
    int t  = rt % Tn;
    int n  = rt / Tn;
    int b  = n >> 9, c = n & (Cn - 1);
    float v1, v2;
    if (f == 0) {
        v1 = pm[(b * Tn + t) * Cn + c];
        v2 = v1;
    } else {
        v1 = ft[((b * 2 * Tn + t)       * Cn + c) * 13 + (f - 1)];
        v2 = ft[((b * 2 * Tn + Tn + t)  * Cn + c) * 13 + (f - 1)];
    }
    d_xn [idx] = v1;
    d_xn2[idx] = v2;
}

// ---------------- packed f32x2 helpers ----------------------------------------
__device__ __forceinline__ uint64_t pack2(float v) {
    uint64_t r;
    asm("mov.b64 %0, {%1, %1};" : "=l"(r) : "f"(v));
    return r;
}
__device__ __forceinline__ void fma2(uint64_t& acc, uint64_t a, uint64_t b) {
    asm("fma.rn.f32x2 %0, %1, %2, %0;" : "+l"(acc) : "l"(a), "l"(b));
}
__device__ __forceinline__ float2 unpack2(uint64_t v) {
    float lo, hi;
    asm("mov.b64 {%0, %1}, %2;" : "=f"(lo), "=f"(hi) : "l"(v));
    return make_float2(lo, hi);
}

// ---------------- register-tiled matmul --------------------------------------
template<int KD, int NOUT, bool RELU>
__device__ __forceinline__ void mmT(const float* __restrict__ sIN,
                                    const float* __restrict__ W,
                                    const float* __restrict__ bias,
                                    float* __restrict__ sOUT, int tid) {
    constexpr int RG = Rn / 4;                    // 12 row groups
    constexpr int TILES = RG * (NOUT / 4);
    for (int tile = tid; tile < TILES; tile += NT) {
        int rg = tile % RG, cg = tile / RG;
        const float* aP = sIN + rg * 4;
        const float* wP = W + cg * 4;
        uint64_t acc[8];
        #pragma unroll
        for (int j = 0; j < 4; j++) {
            uint64_t bp = pack2(__ldg(bias + cg * 4 + j));
            acc[2 * j]     = bp;
            acc[2 * j + 1] = bp;
        }
        #pragma unroll 4
        for (int k = 0; k < KD; k++) {
            ulonglong2 av = *(const ulonglong2*)(aP + k * Rn);
            float4 w = __ldg((const float4*)(wP + k * NOUT));
            uint64_t w0 = pack2(w.x), w1 = pack2(w.y), w2 = pack2(w.z), w3 = pack2(w.w);
            fma2(acc[0], av.x, w0); fma2(acc[1], av.y, w0);
            fma2(acc[2], av.x, w1); fma2(acc[3], av.y, w1);
            fma2(acc[4], av.x, w2); fma2(acc[5], av.y, w2);
            fma2(acc[6], av.x, w3); fma2(acc[7], av.y, w3);
        }
        #pragma unroll
        for (int j = 0; j < 4; j++) {
            float2 lo = unpack2(acc[2 * j]);
            float2 hi = unpack2(acc[2 * j + 1]);
            float4 c;
            c.x = lo.x; c.y = lo.y; c.z = hi.x; c.w = hi.y;
            if (RELU) {
                c.x = fmaxf(c.x, 0.f); c.y = fmaxf(c.y, 0.f);
                c.z = fmaxf(c.z, 0.f); c.w = fmaxf(c.w, 0.f);
            }
            *(float4*)(sOUT + (cg * 4 + j) * Rn + rg * 4) = c;
        }
    }
}

// ---------------- LN helper: 96 threads, 2 per row, shfl combine --------------
__device__ __forceinline__ void layernorm2(float* __restrict__ h,
                                           const float* __restrict__ res,
                                           const float* __restrict__ g,
                                           const float* __restrict__ bb,
                                           int tid) {
    if (tid < 96) {
        int r = tid >> 1, half = tid & 1;
        float vloc[18];
        float m = 0.0f, q2 = 0.0f;
        #pragma unroll
        for (int kk = 0; kk < 18; kk++) {
            int k = half * 18 + kk;
            float v = h[k * Rn + r] + res[k * Rn + r];
            vloc[kk] = v;
            m += v; q2 += v * v;
        }
        m  += __shfl_xor_sync(0xffffffffu, m, 1);
        q2 += __shfl_xor_sync(0xffffffffu, q2, 1);
        m *= (1.0f / HIDn);
        float var = q2 * (1.0f / HIDn) - m * m;
        float rs = rsqrtf(var + 1e-5f);
        #pragma unroll
        for (int kk = 0; kk < 18; kk++) {
            int k = half * 18 + kk;
            h[k * Rn + r] = (vloc[kk] - m) * rs * __ldg(g + k) + __ldg(bb + k);
        }
    }
}

// ---------------- K5: mega-kernel — 2 sequences per CTA, static smem ----------
__global__ __launch_bounds__(NT, 5)
void k_mega(const float* __restrict__ W0,  const float* __restrict__ W1,
            const float* __restrict__ cb,
            const float* __restrict__ tinW, const float* __restrict__ tinb,
            const float* __restrict__ Wq, const float* __restrict__ bq,
            const float* __restrict__ Wk, const float* __restrict__ bk,
            const float* __restrict__ Wv, const float* __restrict__ bv,
            const float* __restrict__ Wo, const float* __restrict__ bo,
            const float* __restrict__ g1, const float* __restrict__ b1,
            const float* __restrict__ fW1, const float* __restrict__ fb1,
            const float* __restrict__ fW2, const float* __restrict__ fb2,
            const float* __restrict__ g2, const float* __restrict__ b2,
            const float* __restrict__ fcW, const float* __restrict__ fcb,
            float* __restrict__ out) {
    __shared__ __align__(16) float sh_h[HIDn * Rn];     // 1728
    __shared__ __align__(16) float sh_U[FFNn * Rn];     // 6912
    __shared__ __align__(16) float sh_S[2304];

    float* h = sh_h;
    float* U = sh_U;
    float* S = sh_S;
    float* x   = U;            //  672
    float* tx  = U + 672;      //  672
    float* cat = U + 1344;     // 1344

    const int tid = threadIdx.x;
    const int nbase = blockIdx.x * SEQ;

    // ---- stage self tiles (col-major [14][48]) ----
    for (int idx = tid; idx < SEQ * Tn * INF; idx += NT) {
        int s2 = idx / 336, u = idx % 336;
        int t = u / INF, f = u % INF;
        int n2 = nbase + s2;
        x  [f * Rn + s2 * Tn + t] = d_xn [n2 * 336 + u];
        cat[f * Rn + s2 * Tn + t] = d_xn2[n2 * 336 + u];
    }

    // ---- ChebConv gather: 64 threads per sequence, next-edge prefetch ----
    {
        int s2 = tid >> 6, l = tid & 63;
        int n2 = nbase + s2;
        int b = n2 >> 9, c = n2 & (Cn - 1);
        float acc[6];
        #pragma unroll
        for (int i = 0; i < 6; i++) acc[i] = 0.0f;
        int start = d_off[c], end = d_off[c + 1];
        int   rr_n = (start < end) ? __ldg(d_brow + start) : 0;
        float w_n  = (start < end) ? __ldg(d_bw + start)   : 0.0f;
        for (int e = start; e < end; e++) {
            int   rr = rr_n;
            float w  = w_n;
            if (e + 1 < end) {
                rr_n = __ldg(d_brow + e + 1);
                w_n  = __ldg(d_bw + e + 1);
            }
            const float* nb = d_xn + (b * Cn + rr) * 336;
            #pragma unroll
            for (int i = 0; i < 6; i++) {
                int u = l + i * 64;
                if (u < 336) acc[i] = fmaf(w, nb[u], acc[i]);
            }
        }
        #pragma unroll
        for (int i = 0; i < 6; i++) {
            int u = l + i * 64;
            if (u < 336) {
                int t = u / INF, f = u % INF;
                tx[f * Rn + s2 * Tn + t] = acc[i];
            }
        }
    }
    __syncthreads();

    // ---- gate: cat[:,14:] = sigmoid(x @ W0 + tx @ W1 + cb) ----
    for (int idx = tid; idx < Rn * INF; idx += NT) {
        int r = idx % Rn, j = idx / Rn;
        float sacc = __ldg(cb + j);
        #pragma unroll
        for (int f = 0; f < INF; f++) {
            sacc = fmaf(x [f * Rn + r], __ldg(W0 + f * INF + j), sacc);
            sacc = fmaf(tx[f * Rn + r], __ldg(W1 + f * INF + j), sacc);
        }
        cat[(INF + j) * Rn + r] = __fdividef(1.0f, 1.0f + __expf(-sacc));
    }
    __syncthreads();

    // ---- h = cat @ tinW + tinb ----
    mmT<28, HIDn, false>(cat, tinW, tinb, h, tid);
    __syncthreads();

    // ---- add PE from precomputed table ----
    for (int idx = tid; idx < HIDn * Rn; idx += NT) {
        int r = idx % Rn, o = idx / Rn;
        int t = r % Tn;
        h[idx] += __ldg(d_pe + o * Tn + t);
    }
    __syncthreads();

    // ---- 2 encoder layers ----
    const float scale = 0.23570226039551584f;  // 1/sqrt(18)
    #pragma unroll 1
    for (int l = 0; l < 2; l++) {
        const float* Wq_l = Wq + l * HIDn * HIDn;  const float* bq_l = bq + l * HIDn;
        const float* Wk_l = Wk + l * HIDn * HIDn;  const float* bk_l = bk + l * HIDn;
        const float* Wv_l = Wv + l * HIDn * HIDn;  const float* bv_l = bv + l * HIDn;
        const float* Wo_l = Wo + l * HIDn * HIDn;  const float* bo_l = bo + l * HIDn;
        const float* g1_l = g1 + l * HIDn;         const float* b1_l = b1 + l * HIDn;
        const float* g2_l = g2 + l * HIDn;         const float* b2_l = b2 + l * HIDn;
        const float* fW1_l = fW1 + l * HIDn * FFNn; const float* fb1_l = fb1 + l * FFNn;
        const float* fW2_l = fW2 + l * FFNn * HIDn; const float* fb2_l = fb2 + l * HIDn;

        mmT<HIDn, HIDn, false>(h, Wq_l, bq_l, U,        tid);
        mmT<HIDn, HIDn, false>(h, Wk_l, bk_l, U + 1728, tid);
        mmT<HIDn, HIDn, false>(h, Wv_l, bv_l, U + 3456, tid);
        __syncthreads();

        // ---- scores: register-tiled 24x24x18 GEMMs per (s2,hh) block ----
        for (int tile = tid; tile < 144; tile += NT) {
            int bs = tile / 36, rem = tile % 36;
            int ig = rem % 6, jg = rem / 6;
            int s2 = bs >> 1, hh = bs & 1;
            const float* qb = U        + hh * HDn * Rn + s2 * Tn + ig * 4;
            const float* kb = U + 1728 + hh * HDn * Rn + s2 * Tn + jg * 4;
            uint64_t acc[8];
            #pragma unroll
            for (int i = 0; i < 8; i++) acc[i] = 0ull;
            #pragma unroll 2
            for (int d = 0; d < HDn; d++) {
                ulonglong2 qv = *(const ulonglong2*)(qb + d * Rn);
                float4 kv = *(const float4*)(kb + d * Rn);
                uint64_t k0 = pack2(kv.x), k1 = pack2(kv.y), k2 = pack2(kv.z), k3 = pack2(kv.w);
                fma2(acc[0], qv.x, k0); fma2(acc[1], qv.y, k0);
                fma2(acc[2], qv.x, k1); fma2(acc[3], qv.y, k1);
                fma2(acc[4], qv.x, k2); fma2(acc[5], qv.y, k2);
                fma2(acc[6], qv.x, k3); fma2(acc[7], qv.y, k3);
            }
            int rowbase = s2 * 48 + hh * 24 + ig * 4;
            #pragma unroll
            for (int jj = 0; jj < 4; jj++) {
                float2 lo = unpack2(acc[2 * jj]);
                float2 hi = unpack2(acc[2 * jj + 1]);
                *(float4*)(S + (jg * 4 + jj) * 96 + rowbase) =
                    make_float4(lo.x * scale, lo.y * scale, hi.x * scale, hi.y * scale);
            }
        }
        __syncthreads();

        // softmax over j (row per thread; stride-96)
        if (tid < 96) {
            float m = S[tid];
            #pragma unroll
            for (int j = 1; j < Tn; j++) m = fmaxf(m, S[j * 96 + tid]);
            float sum = 0.0f;
            #pragma unroll
            for (int j = 0; j < Tn; j++) {
                float e = __expf(S[j * 96 + tid] - m);
                S[j * 96 + tid] = e;
                sum += e;
            }
            float inv = __fdividef(1.0f, sum);
            #pragma unroll
            for (int j = 0; j < Tn; j++) S[j * 96 + tid] *= inv;
        }
        __syncthreads();

        // ---- attn out: register-tiled A@V -> q region (U[0..1728)) ----
        for (int tile = tid; tile < 144; tile += NT) {
            int s2 = tile / 72, rem = tile % 72;
            int tg = rem % 6, og = rem / 6;     // og 0..11
            int hh = og / 6;
            const float* ab = S + s2 * 48 + hh * 24 + tg * 4;       // + j*96
            const float* vb = U + 3456 + (og * 3) * Rn + s2 * Tn;   // + oo*Rn + j
            uint64_t acc[6];
            #pragma unroll
            for (int i = 0; i < 6; i++) acc[i] = 0ull;
            #pragma unroll 4
            for (int j = 0; j < Tn; j++) {
                ulonglong2 avv = *(const ulonglong2*)(ab + j * 96);
                uint64_t p0 = pack2(vb[j]);
                uint64_t p1 = pack2(vb[Rn + j]);
                uint64_t p2 = pack2(vb[2 * Rn + j]);
                fma2(acc[0], avv.x, p0); fma2(acc[1], avv.y, p0);
                fma2(acc[2], avv.x, p1); fma2(acc[3], avv.y, p1);
                fma2(acc[4], avv.x, p2); fma2(acc[5], avv.y, p2);
            }
            #pragma unroll
            for (int oo = 0; oo < 3; oo++) {
                float2 lo = unpack2(acc[2 * oo]);
                float2 hi = unpack2(acc[2 * oo + 1]);
                *(float4*)(U + (og * 3 + oo) * Rn + s2 * Tn + tg * 4) =
                    make_float4(lo.x, lo.y, hi.x, hi.y);
            }
        }
        __syncthreads();

        mmT<HIDn, HIDn, false>(U, Wo_l, bo_l, U + 5184, tid);
        __syncthreads();

        // LN1: h = LN(h + o)
        layernorm2(h, U + 5184, g1_l, b1_l, tid);
        __syncthreads();

        // FFN
        mmT<HIDn, FFNn, true >(h, fW1_l, fb1_l, U, tid);
        __syncthreads();
        mmT<FFNn, HIDn, false>(U, fW2_l, fb2_l, S, tid);
        __syncthreads();

        // LN2: h = LN(h + f2)
        layernorm2(h, S, g2_l, b2_l, tid);
        __syncthreads();
    }

    // ---- final fc + store ----
    if (tid < Rn) {
        int r = tid;
        int s2 = r / Tn, t = r % Tn;
        int n2 = nbase + s2;
        int b = n2 >> 9, c = n2 & (Cn - 1);
        float acc = __ldg(fcb);
        #pragma unroll
        for (int k = 0; k < HIDn; k++) acc = fmaf(h[k * Rn + r], __ldg(fcW + k), acc);
        out[(b * Tn + t) * Cn + c] = acc;
    }
}

// ---------------- launch ------------------------------------------------------
extern "C" void kernel_launch(void* const* d_in, const int* in_sizes, int n_in,
                              void* d_out, int out_size) {
    const float *pm, *ft, *W0, *W1, *cb, *tinW, *tinb, *Wq, *bq, *Wk, *bk,
                *Wv, *bv, *Wo, *bo, *g1, *b1, *fW1, *fb1, *fW2, *fb2,
                *g2, *b2, *fcW, *fcb;
    const int* ei;

    if (in_sizes[2] == 2 * EG) {
        pm  = (const float*)d_in[0];  ft  = (const float*)d_in[1];
        ei  = (const int*)  d_in[2];
        W0  = (const float*)d_in[3];  W1  = (const float*)d_in[4];
        cb  = (const float*)d_in[5];
        tinW= (const float*)d_in[6];  tinb= (const float*)d_in[7];
        Wq  = (const float*)d_in[8];  bq  = (const float*)d_in[9];
        Wk  = (const float*)d_in[10]; bk  = (const float*)d_in[11];
        Wv  = (const float*)d_in[12]; bv  = (const float*)d_in[13];
        Wo  = (const float*)d_in[14]; bo  = (const float*)d_in[15];
        g1  = (const float*)d_in[16]; b1  = (const float*)d_in[17];
        fW1 = (const float*)d_in[18]; fb1 = (const float*)d_in[19];
        fW2 = (const float*)d_in[20]; fb2 = (const float*)d_in[21];
        g2  = (const float*)d_in[22]; b2  = (const float*)d_in[23];
        fcW = (const float*)d_in[24]; fcb = (const float*)d_in[25];
    } else {
        pm  = (const float*)d_in[0];  ft  = (const float*)d_in[1];
        W0  = (const float*)d_in[2];  W1  = (const float*)d_in[3];
        cb  = (const float*)d_in[4];
        tinW= (const float*)d_in[5];  tinb= (const float*)d_in[6];
        Wq  = (const float*)d_in[7];  bq  = (const float*)d_in[8];
        Wk  = (const float*)d_in[9];  bk  = (const float*)d_in[10];
        Wv  = (const float*)d_in[11]; bv  = (const float*)d_in[12];
        Wo  = (const float*)d_in[13]; bo  = (const float*)d_in[14];
        g1  = (const float*)d_in[15]; b1  = (const float*)d_in[16];
        fW1 = (const float*)d_in[17]; fb1 = (const float*)d_in[18];
        fW2 = (const float*)d_in[19]; fb2 = (const float*)d_in[20];
        g2  = (const float*)d_in[21]; b2  = (const float*)d_in[22];
        fcW = (const float*)d_in[23]; fcb = (const float*)d_in[24];
        ei  = (const int*)  d_in[25];
    }

    k_count<<<Cn, 32>>>(ei);
    k_scan <<<1, Cn>>>();
    k_fill <<<Cn, 32>>>(ei);
    {
        int total = Nn * Tn * INF;
        k_pack<<<(total + 255) / 256, 256>>>(pm, ft);
    }
    k_mega<<<Nn / SEQ, NT>>>(W0, W1, cb, tinW, tinb,
                             Wq, bq, Wk, bk, Wv, bv, Wo, bo,
                             g1, b1, fW1, fb1, fW2, fb2, g2, b2,
                             fcW, fcb, (float*)d_out);
}

// round 10
// speedup vs baseline: 1.1299x; 1.1299x over previous
#include <cuda_runtime.h>
#include <cuda_bf16.h>
#include <math.h>
#include <stdint.h>

#define Bn   32
#define Tn   24
#define Cn   512
#define Nn   (Bn*Cn)
#define INF  14
#define HIDn 36
#define FFNn 144
#define HDn  18
#define EG   8192
#define SEQ  2
#define Rn   (SEQ*Tn)         // 48 rows per CTA
#define NT   128

// ---------------- scratch (device globals) -----------------------------------
__device__ float d_xn [Nn*Tn*INF];
__device__ float d_xn2[Nn*Tn*INF];
__device__ int   d_deg[Cn];
__device__ int   d_colcnt[Cn];
__device__ int   d_off[Cn+1];
__device__ float d_dinv[Cn];
__device__ int   d_brow[EG];
__device__ float d_bw[EG];
__device__ float d_pe[HIDn*Tn];

// bf16-split weights, [n][k] as bf16x2 pairs (uint32), hi/lo planes.
// TIN [40][16]@0; QKVO 8x[40][24]@640; F1 2x[144][24]@8320; F2 2x[40][72]@15232
#define WB_TOT   20992
#define OFF_QKVO 640
#define OFF_F1   8320
#define OFF_F2   15232
__device__ uint32_t d_wbh[WB_TOT];
__device__ uint32_t d_wbl[WB_TOT];

// ---------------- K1 ----------------------------------------------------------
__global__ void k_count(const int* __restrict__ ei) {
    int c = blockIdx.x, lane = threadIdx.x;
    int cr = 0, cc = 0;
    for (int e = lane; e < EG; e += 32) {
        cr += (ei[e]      == c);
        cc += (ei[EG + e] == c);
    }
    #pragma unroll
    for (int o = 16; o; o >>= 1) {
        cr += __shfl_down_sync(0xffffffffu, cr, o);
        cc += __shfl_down_sync(0xffffffffu, cc, o);
    }
    if (lane == 0) { d_deg[c] = cr; d_colcnt[c] = cc; }
}

// ---------------- K2 ----------------------------------------------------------
__global__ void k_scan() {
    __shared__ int s[Cn];
    int t = threadIdx.x;
    s[t] = d_colcnt[t];
    __syncthreads();
    for (int o = 1; o < Cn; o <<= 1) {
        int v = (t >= o) ? s[t - o] : 0;
        __syncthreads();
        s[t] += v;
        __syncthreads();
    }
    d_off[t + 1] = s[t];
    if (t == 0) d_off[0] = 0;
    int dg = d_deg[t];
    d_dinv[t] = (dg > 0) ? (1.0f / sqrtf((float)dg)) : 0.0f;
    for (int i = t; i < HIDn * Tn; i += Cn) {
        int o = i / Tn, tt = i % Tn;
        float div = expf(-9.210340371976184f * (float)(o & ~1) / (float)HIDn);
        float ang = (float)tt * div;
        d_pe[i] = (o & 1) ? cosf(ang) : sinf(ang);
    }
}

// ---------------- K3 ----------------------------------------------------------
__global__ void k_fill(const int* __restrict__ ei) {
    int c = blockIdx.x, lane = threadIdx.x;
    int base = d_off[c];
    float dc = d_dinv[c];
    for (int e0 = 0; e0 < EG; e0 += 32) {
        int e = e0 + lane;
        int col = ei[EG + e];
        bool m = (col == c);
        unsigned mask = __ballot_sync(0xffffffffu, m);
        if (m) {
            int pos = base + __popc(mask & ((1u << lane) - 1u));
            int r = ei[e];
            d_brow[pos] = r;
            d_bw[pos]   = -(d_dinv[r] * dc);
        }
        base += __popc(mask);
    }
}

// ---------------- K4 ----------------------------------------------------------
__global__ void k_pack(const float* __restrict__ pm, const float* __restrict__ ft) {
    int idx = blockIdx.x * blockDim.x + threadIdx.x;
    if (idx >= Nn * Tn * INF) return;
    int f  = idx % INF;
    int rt = idx / INF;
    int t  = rt % Tn;
    int n  = rt / Tn;
    int b  = n >> 9, c = n & (Cn - 1);
    float v1, v2;
    if (f == 0) {
        v1 = pm[(b * Tn + t) * Cn + c];
        v2 = v1;
    } else {
        v1 = ft[((b * 2 * Tn + t)      * Cn + c) * 13 + (f - 1)];
        v2 = ft[((b * 2 * Tn + Tn + t) * Cn + c) * 13 + (f - 1)];
    }
    d_xn [idx] = v1;
    d_xn2[idx] = v2;
}

// ---------------- K5: weight bf16 hi/lo split ---------------------------------
__global__ void k_wprep(const float* __restrict__ tinW,
                        const float* __restrict__ Wq, const float* __restrict__ Wk,
                        const float* __restrict__ Wv, const float* __restrict__ Wo,
                        const float* __restrict__ fW1, const float* __restrict__ fW2) {
    int u = blockIdx.x * blockDim.x + threadIdx.x;
    if (u >= WB_TOT) return;
    float v0 = 0.0f, v1 = 0.0f;
    if (u < OFF_QKVO) {                       // tin: dest [40][16], src [28][36]
        int n = u / 16, p = u % 16, k = 2 * p;
        if (n < 36) {
            if (k < 28)     v0 = tinW[k * 36 + n];
            if (k + 1 < 28) v1 = tinW[(k + 1) * 36 + n];
        }
    } else if (u < OFF_F1) {                  // qkvo: 8 mats [40][24], src [36][36]
        int q = u - OFF_QKVO;
        int mat = q / 960, r = q % 960;
        int l = mat >> 2, w = mat & 3;
        int n = r / 24, p = r % 24, k = 2 * p;
        const float* W = (w == 0 ? Wq : w == 1 ? Wk : w == 2 ? Wv : Wo) + l * 1296;
        if (n < 36) {
            if (k < 36)     v0 = W[k * 36 + n];
            if (k + 1 < 36) v1 = W[(k + 1) * 36 + n];
        }
    } else if (u < OFF_F2) {                  // f1: [144][24], src [36][144]
        int q = u - OFF_F1;
        int l = q / 3456, r = q % 3456;
        int n = r / 24, p = r % 24, k = 2 * p;
        const float* W = fW1 + l * 5184;
        if (k < 36)     v0 = W[k * 144 + n];
        if (k + 1 < 36) v1 = W[(k + 1) * 144 + n];
    } else {                                  // f2: [40][72], src [144][36]
        int q = u - OFF_F2;
        int l = q / 2880, r = q % 2880;
        int n = r / 72, p = r % 72, k = 2 * p;
        const float* W = fW2 + l * 5184;
        if (n < 36) {
            v0 = W[k * 36 + n];
            v1 = W[(k + 1) * 36 + n];
        }
    }
    __nv_bfloat16 h0 = __float2bfloat16_rn(v0);
    __nv_bfloat16 h1 = __float2bfloat16_rn(v1);
    __nv_bfloat16 l0 = __float2bfloat16_rn(v0 - __bfloat162float(h0));
    __nv_bfloat16 l1 = __float2bfloat16_rn(v1 - __bfloat162float(h1));
    d_wbh[u] = (uint32_t)__bfloat16_as_ushort(h0) | ((uint32_t)__bfloat16_as_ushort(h1) << 16);
    d_wbl[u] = (uint32_t)__bfloat16_as_ushort(l0) | ((uint32_t)__bfloat16_as_ushort(l1) << 16);
}

// ---------------- tensor-core helpers -----------------------------------------
template<int KP>
__device__ __forceinline__ int swzm(int m) {
    if (KP == 48) return ((m >> 2) & 1) << 4;
    else          return ((((m >> 1) & 1) << 4) | (((m >> 2) & 1) << 5));  // KP==32
}

// stage fp32 col-major [KD][48] -> S row-major bf16 [48][KP], hi+lo planes
template<int KP, int KD>
__device__ __forceinline__ void stageA(const float* __restrict__ IN, float* Sb, int tid) {
    uint32_t* H = reinterpret_cast<uint32_t*>(Sb);
    constexpr int PLANE = 48 * KP / 2;          // uints per plane
    for (int u = tid; u < PLANE; u += NT) {
        int m = u % 48, p = u / 48;
        int k = 2 * p;
        float v0 = (k     < KD) ? IN[k * 48 + m]       : 0.0f;
        float v1 = (k + 1 < KD) ? IN[(k + 1) * 48 + m] : 0.0f;
        __nv_bfloat16 h0 = __float2bfloat16_rn(v0);
        __nv_bfloat16 h1 = __float2bfloat16_rn(v1);
        __nv_bfloat16 l0 = __float2bfloat16_rn(v0 - __bfloat162float(h0));
        __nv_bfloat16 l1 = __float2bfloat16_rn(v1 - __bfloat162float(h1));
        int idx = ((m * (KP * 2) + p * 4) ^ swzm<KP>(m)) >> 2;
        H[idx]         = (uint32_t)__bfloat16_as_ushort(h0) | ((uint32_t)__bfloat16_as_ushort(h1) << 16);
        H[PLANE + idx] = (uint32_t)__bfloat16_as_ushort(l0) | ((uint32_t)__bfloat16_as_ushort(l1) << 16);
    }
}

__device__ __forceinline__ void ldm4(uint32_t& r0, uint32_t& r1, uint32_t& r2, uint32_t& r3,
                                     uint32_t addr) {
    asm volatile("ldmatrix.sync.aligned.m8n8.x4.shared.b16 {%0,%1,%2,%3}, [%4];"
                 : "=r"(r0), "=r"(r1), "=r"(r2), "=r"(r3) : "r"(addr));
}

__device__ __forceinline__ void mma_bf16(float& c0, float& c1, float& c2, float& c3,
                                         uint32_t a0, uint32_t a1, uint32_t a2, uint32_t a3,
                                         uint32_t b0, uint32_t b1) {
    asm volatile("mma.sync.aligned.m16n8k16.row.col.f32.bf16.bf16.f32 "
                 "{%0,%1,%2,%3}, {%4,%5,%6,%7}, {%8,%9}, {%0,%1,%2,%3};"
                 : "+f"(c0), "+f"(c1), "+f"(c2), "+f"(c3)
                 : "r"(a0), "r"(a1), "r"(a2), "r"(a3), "r"(b0), "r"(b1));
}

// OUT[NOUT][48] col-major fp32 = W^T @ staged-A (+bias). No internal syncs.
template<int KP, int NOUT, bool RELU>
__device__ void tmmC(const float* Sb,
                     const uint32_t* __restrict__ wh, const uint32_t* __restrict__ wl,
                     const float* __restrict__ bias, float* __restrict__ OUT,
                     int warp, int lane) {
    constexpr int NTN = (NOUT + 7) / 8;
    constexpr int MYN = (NTN + 3) / 4;
    uint32_t sbase = (uint32_t)__cvta_generic_to_shared(Sb);
    int part = lane >> 3, rr = lane & 7;
    int g = lane >> 2, q2 = (lane & 3) * 2;
    #pragma unroll
    for (int mt = 0; mt < 3; mt++) {
        float C[MYN][4];
        #pragma unroll
        for (int i = 0; i < MYN; i++) { C[i][0]=0.f; C[i][1]=0.f; C[i][2]=0.f; C[i][3]=0.f; }
        #pragma unroll
        for (int kt = 0; kt < KP / 16; kt++) {
            int m = mt * 16 + rr + (part & 1) * 8;
            int colb = (kt * 16 + ((part >> 1) << 3)) * 2;
            uint32_t off = (uint32_t)((m * (KP * 2) + colb) ^ swzm<KP>(m));
            uint32_t ah0, ah1, ah2, ah3, al0, al1, al2, al3;
            ldm4(ah0, ah1, ah2, ah3, sbase + off);
            ldm4(al0, al1, al2, al3, sbase + 48 * KP * 2 + off);
            #pragma unroll
            for (int i = 0; i < MYN; i++) {
                int nt = warp + 4 * i;
                if (nt < NTN) {
                    int pi = (nt * 8 + g) * (KP / 2) + kt * 8 + (lane & 3);
                    uint32_t bh0 = __ldg(wh + pi), bh1 = __ldg(wh + pi + 4);
                    uint32_t bl0 = __ldg(wl + pi), bl1 = __ldg(wl + pi + 4);
                    mma_bf16(C[i][0], C[i][1], C[i][2], C[i][3], ah0, ah1, ah2, ah3, bh0, bh1);
                    mma_bf16(C[i][0], C[i][1], C[i][2], C[i][3], ah0, ah1, ah2, ah3, bl0, bl1);
                    mma_bf16(C[i][0], C[i][1], C[i][2], C[i][3], al0, al1, al2, al3, bh0, bh1);
                }
            }
        }
        #pragma unroll
        for (int i = 0; i < MYN; i++) {
            int nt = warp + 4 * i;
            if (nt < NTN) {
                int m = mt * 16 + g;
                int nA = nt * 8 + q2, nB = nA + 1;
                if ((NOUT & 7) == 0 || nA < NOUT) {
                    float bv = __ldg(bias + nA);
                    float a0 = C[i][0] + bv, a2 = C[i][2] + bv;
                    if (RELU) { a0 = fmaxf(a0, 0.f); a2 = fmaxf(a2, 0.f); }
                    OUT[nA * 48 + m] = a0; OUT[nA * 48 + m + 8] = a2;
                }
                if ((NOUT & 7) == 0 || nB < NOUT) {
                    float bv = __ldg(bias + nB);
                    float a1 = C[i][1] + bv, a3 = C[i][3] + bv;
                    if (RELU) { a1 = fmaxf(a1, 0.f); a3 = fmaxf(a3, 0.f); }
                    OUT[nB * 48 + m] = a1; OUT[nB * 48 + m + 8] = a3;
                }
            }
        }
    }
}

// ffn2: OUT[36][48] = fW2^T @ Uin[144][48] via 3 staged K-chunks; OUT = Sb after last chunk
__device__ void tmm_ffn2(float* Sb, const float* __restrict__ Uin,
                         const uint32_t* __restrict__ wh, const uint32_t* __restrict__ wl,
                         const float* __restrict__ bias, float* __restrict__ OUT,
                         int warp, int lane, int tid) {
    float C[3][2][4];
    #pragma unroll
    for (int a = 0; a < 3; a++)
        #pragma unroll
        for (int b = 0; b < 2; b++) { C[a][b][0]=0.f; C[a][b][1]=0.f; C[a][b][2]=0.f; C[a][b][3]=0.f; }
    uint32_t sbase = (uint32_t)__cvta_generic_to_shared(Sb);
    int part = lane >> 3, rr = lane & 7;
    int g = lane >> 2, q2 = (lane & 3) * 2;
    for (int ch = 0; ch < 3; ch++) {
        __syncthreads();                       // prior S readers done
        stageA<48, 48>(Uin + ch * 2304, Sb, tid);
        __syncthreads();
        #pragma unroll
        for (int mt = 0; mt < 3; mt++) {
            #pragma unroll
            for (int kt = 0; kt < 3; kt++) {
                int m = mt * 16 + rr + (part & 1) * 8;
                int colb = (kt * 16 + ((part >> 1) << 3)) * 2;
                uint32_t off = (uint32_t)((m * 96 + colb) ^ swzm<48>(m));
                uint32_t ah0, ah1, ah2, ah3, al0, al1, al2, al3;
                ldm4(ah0, ah1, ah2, ah3, sbase + off);
                ldm4(al0, al1, al2, al3, sbase + 4608 + off);
                #pragma unroll
                for (int i = 0; i < 2; i++) {
                    int nt = warp + 4 * i;
                    if (nt < 5) {
                        int pi = (nt * 8 + g) * 72 + ch * 24 + kt * 8 + (lane & 3);
                        uint32_t bh0 = __ldg(wh + pi), bh1 = __ldg(wh + pi + 4);
                        uint32_t bl0 = __ldg(wl + pi), bl1 = __ldg(wl + pi + 4);
                        mma_bf16(C[mt][i][0], C[mt][i][1], C[mt][i][2], C[mt][i][3],
                                 ah0, ah1, ah2, ah3, bh0, bh1);
                        mma_bf16(C[mt][i][0], C[mt][i][1], C[mt][i][2], C[mt][i][3],
                                 ah0, ah1, ah2, ah3, bl0, bl1);
                        mma_bf16(C[mt][i][0], C[mt][i][1], C[mt][i][2], C[mt][i][3],
                                 al0, al1, al2, al3, bh0, bh1);
                    }
                }
            }
        }
    }
    __syncthreads();                           // all reads of staged S done before OUT=S write
    #pragma unroll
    for (int mt = 0; mt < 3; mt++)
        #pragma unroll
        for (int i = 0; i < 2; i++) {
            int nt = warp + 4 * i;
            if (nt < 5) {
                int m = mt * 16 + g;
                int nA = nt * 8 + q2, nB = nA + 1;
                if (nA < 36) {
                    float bv = __ldg(bias + nA);
                    OUT[nA * 48 + m] = C[mt][i][0] + bv;
                    OUT[nA * 48 + m + 8] = C[mt][i][2] + bv;
                }
                if (nB < 36) {
                    float bv = __ldg(bias + nB);
                    OUT[nB * 48 + m] = C[mt][i][1] + bv;
                    OUT[nB * 48 + m + 8] = C[mt][i][3] + bv;
                }
            }
        }
}

// ---------------- scalar helpers ----------------------------------------------
__device__ __forceinline__ uint64_t pack2(float v) {
    uint64_t r;
    asm("mov.b64 %0, {%1, %1};" : "=l"(r) : "f"(v));
    return r;
}
__device__ __forceinline__ void fma2(uint64_t& acc, uint64_t a, uint64_t b) {
    asm("fma.rn.f32x2 %0, %1, %2, %0;" : "+l"(acc) : "l"(a), "l"(b));
}
__device__ __forceinline__ float2 unpack2(uint64_t v) {
    float lo, hi;
    asm("mov.b64 {%0, %1}, %2;" : "=f"(lo), "=f"(hi) : "l"(v));
    return make_float2(lo, hi);
}

__device__ __forceinline__ void layernorm2(float* __restrict__ h,
                                           const float* __restrict__ res,
                                           const float* __restrict__ g,
                                           const float* __restrict__ bb,
                                           int tid) {
    if (tid < 96) {
        int r = tid >> 1, half = tid & 1;
        float vloc[18];
        float m = 0.0f, q2 = 0.0f;
        #pragma unroll
        for (int kk = 0; kk < 18; kk++) {
            int k = half * 18 + kk;
            float v = h[k * Rn + r] + res[k * Rn + r];
            vloc[kk] = v;
            m += v; q2 += v * v;
        }
        m  += __shfl_xor_sync(0xffffffffu, m, 1);
        q2 += __shfl_xor_sync(0xffffffffu, q2, 1);
        m *= (1.0f / HIDn);
        float var = q2 * (1.0f / HIDn) - m * m;
        float rs = rsqrtf(var + 1e-5f);
        #pragma unroll
        for (int kk = 0; kk < 18; kk++) {
            int k = half * 18 + kk;
            h[k * Rn + r] = (vloc[kk] - m) * rs * __ldg(g + k) + __ldg(bb + k);
        }
    }
}

// ---------------- K6: mega-kernel ---------------------------------------------
__global__ __launch_bounds__(NT, 5)
void k_mega(const float* __restrict__ W0,  const float* __restrict__ W1,
            const float* __restrict__ cb,  const float* __restrict__ tinb,
            const float* __restrict__ bq,  const float* __restrict__ bk,
            const float* __restrict__ bv,  const float* __restrict__ bo,
            const float* __restrict__ g1,  const float* __restrict__ b1,
            const float* __restrict__ fb1, const float* __restrict__ fb2,
            const float* __restrict__ g2,  const float* __restrict__ b2,
            const float* __restrict__ fcW, const float* __restrict__ fcb,
            float* __restrict__ out) {
    __shared__ __align__(16) float sh_h[HIDn * Rn];     // 1728
    __shared__ __align__(16) float sh_U[FFNn * Rn];     // 6912
    __shared__ __align__(16) float sh_S[2304];          // scores / bf16 staging / ffn2 out

    float* h = sh_h;
    float* U = sh_U;
    float* S = sh_S;
    float* x   = U;
    float* tx  = U + 672;
    float* cat = U + 1344;

    const int tid = threadIdx.x;
    const int warp = tid >> 5, lane = tid & 31;
    const int nbase = blockIdx.x * SEQ;

    // ---- stage self tiles (col-major [14][48]) ----
    for (int idx = tid; idx < SEQ * Tn * INF; idx += NT) {
        int s2 = idx / 336, u = idx % 336;
        int t = u / INF, f = u % INF;
        int n2 = nbase + s2;
        x  [f * Rn + s2 * Tn + t] = d_xn [n2 * 336 + u];
        cat[f * Rn + s2 * Tn + t] = d_xn2[n2 * 336 + u];
    }

    // ---- ChebConv gather ----
    {
        int s2 = tid >> 6, l = tid & 63;
        int n2 = nbase + s2;
        int b = n2 >> 9, c = n2 & (Cn - 1);
        float acc[6];
        #pragma unroll
        for (int i = 0; i < 6; i++) acc[i] = 0.0f;
        int start = d_off[c], end = d_off[c + 1];
        for (int e = start; e < end; e++) {
            int   rr = __ldg(d_brow + e);
            float w  = __ldg(d_bw + e);
            const float* nb = d_xn + (b * Cn + rr) * 336;
            #pragma unroll
            for (int i = 0; i < 6; i++) {
                int u = l + i * 64;
                if (u < 336) acc[i] = fmaf(w, nb[u], acc[i]);
            }
        }
        #pragma unroll
        for (int i = 0; i < 6; i++) {
            int u = l + i * 64;
            if (u < 336) {
                int t = u / INF, f = u % INF;
                tx[f * Rn + s2 * Tn + t] = acc[i];
            }
        }
    }
    __syncthreads();

    // ---- gate ----
    for (int idx = tid; idx < Rn * INF; idx += NT) {
        int r = idx % Rn, j = idx / Rn;
        float sacc = __ldg(cb + j);
        #pragma unroll
        for (int f = 0; f < INF; f++) {
            sacc = fmaf(x [f * Rn + r], __ldg(W0 + f * INF + j), sacc);
            sacc = fmaf(tx[f * Rn + r], __ldg(W1 + f * INF + j), sacc);
        }
        cat[(INF + j) * Rn + r] = __fdividef(1.0f, 1.0f + __expf(-sacc));
    }
    __syncthreads();

    // ---- tin: h = cat @ tinW + tinb (tensor) ----
    stageA<32, 28>(cat, S, tid);
    __syncthreads();
    tmmC<32, HIDn, false>(S, d_wbh, d_wbl, tinb, h, warp, lane);
    __syncthreads();

    // ---- PE ----
    for (int idx = tid; idx < HIDn * Rn; idx += NT) {
        int r = idx % Rn, o = idx / Rn;
        int t = r % Tn;
        h[idx] += __ldg(d_pe + o * Tn + t);
    }
    __syncthreads();

    const float scale = 0.23570226039551584f;
    #pragma unroll 1
    for (int l = 0; l < 2; l++) {
        const uint32_t* wqh = d_wbh + OFF_QKVO + (l * 4 + 0) * 960;
        const uint32_t* wkh = d_wbh + OFF_QKVO + (l * 4 + 1) * 960;
        const uint32_t* wvh = d_wbh + OFF_QKVO + (l * 4 + 2) * 960;
        const uint32_t* woh = d_wbh + OFF_QKVO + (l * 4 + 3) * 960;
        const uint32_t* wql = d_wbl + OFF_QKVO + (l * 4 + 0) * 960;
        const uint32_t* wkl = d_wbl + OFF_QKVO + (l * 4 + 1) * 960;
        const uint32_t* wvl = d_wbl + OFF_QKVO + (l * 4 + 2) * 960;
        const uint32_t* wol = d_wbl + OFF_QKVO + (l * 4 + 3) * 960;
        const uint32_t* f1h = d_wbh + OFF_F1 + l * 3456;
        const uint32_t* f1l = d_wbl + OFF_F1 + l * 3456;
        const uint32_t* f2h = d_wbh + OFF_F2 + l * 2880;
        const uint32_t* f2l = d_wbl + OFF_F2 + l * 2880;
        const float* bq_l = bq + l * HIDn;  const float* bk_l = bk + l * HIDn;
        const float* bv_l = bv + l * HIDn;  const float* bo_l = bo + l * HIDn;
        const float* g1_l = g1 + l * HIDn;  const float* b1_l = b1 + l * HIDn;
        const float* g2_l = g2 + l * HIDn;  const float* b2_l = b2 + l * HIDn;
        const float* fb1_l = fb1 + l * FFNn; const float* fb2_l = fb2 + l * HIDn;

        // ---- q,k,v from one staged h ----
        stageA<48, 36>(h, S, tid);
        __syncthreads();
        tmmC<48, HIDn, false>(S, wqh, wql, bq_l, U,        warp, lane);
        tmmC<48, HIDn, false>(S, wkh, wkl, bk_l, U + 1728, warp, lane);
        tmmC<48, HIDn, false>(S, wvh, wvl, bv_l, U + 3456, warp, lane);
        __syncthreads();

        // ---- scores (scalar, S now free) ----
        for (int tile = tid; tile < 144; tile += NT) {
            int bs = tile / 36, rem = tile % 36;
            int ig = rem % 6, jg = rem / 6;
            int s2 = bs >> 1, hh = bs & 1;
            const float* qb = U        + hh * HDn * Rn + s2 * Tn + ig * 4;
            const float* kb = U + 1728 + hh * HDn * Rn + s2 * Tn + jg * 4;
            uint64_t acc[8];
            #pragma unroll
            for (int i = 0; i < 8; i++) acc[i] = 0ull;
            #pragma unroll 2
            for (int d = 0; d < HDn; d++) {
                ulonglong2 qv = *(const ulonglong2*)(qb + d * Rn);
                float4 kv = *(const float4*)(kb + d * Rn);
                uint64_t k0 = pack2(kv.x), k1 = pack2(kv.y), k2 = pack2(kv.z), k3 = pack2(kv.w);
                fma2(acc[0], qv.x, k0); fma2(acc[1], qv.y, k0);
                fma2(acc[2], qv.x, k1); fma2(acc[3], qv.y, k1);
                fma2(acc[4], qv.x, k2); fma2(acc[5], qv.y, k2);
                fma2(acc[6], qv.x, k3); fma2(acc[7], qv.y, k3);
            }
            int rowbase = s2 * 48 + hh * 24 + ig * 4;
            #pragma unroll
            for (int jj = 0; jj < 4; jj++) {
                float2 lo = unpack2(acc[2 * jj]);
                float2 hi = unpack2(acc[2 * jj + 1]);
                *(float4*)(S + (jg * 4 + jj) * 96 + rowbase) =
                    make_float4(lo.x * scale, lo.y * scale, hi.x * scale, hi.y * scale);
            }
        }
        __syncthreads();

        // softmax
        if (tid < 96) {
            float m = S[tid];
            #pragma unroll
            for (int j = 1; j < Tn; j++) m = fmaxf(m, S[j * 96 + tid]);
            float sum = 0.0f;
            #pragma unroll
            for (int j = 0; j < Tn; j++) {
                float e = __expf(S[j * 96 + tid] - m);
                S[j * 96 + tid] = e;
                sum += e;
            }
            float inv = __fdividef(1.0f, sum);
            #pragma unroll
            for (int j = 0; j < Tn; j++) S[j * 96 + tid] *= inv;
        }
        __syncthreads();

        // attn out -> U[0..1728)
        for (int tile = tid; tile < 144; tile += NT) {
            int s2 = tile / 72, rem = tile % 72;
            int tg = rem % 6, og = rem / 6;
            int hh = og / 6;
            const float* ab = S + s2 * 48 + hh * 24 + tg * 4;
            const float* vb = U + 3456 + (og * 3) * Rn + s2 * Tn;
            uint64_t acc[6];
            #pragma unroll
            for (int i = 0; i < 6; i++) acc[i] = 0ull;
            #pragma unroll 4
            for (int j = 0; j < Tn; j++) {
                ulonglong2 avv = *(const ulonglong2*)(ab + j * 96);
                uint64_t p0 = pack2(vb[j]);
                uint64_t p1 = pack2(vb[Rn + j]);
                uint64_t p2 = pack2(vb[2 * Rn + j]);
                fma2(acc[0], avv.x, p0); fma2(acc[1], avv.y, p0);
                fma2(acc[2], avv.x, p1); fma2(acc[3], avv.y, p1);
                fma2(acc[4], avv.x, p2); fma2(acc[5], avv.y, p2);
            }
            #pragma unroll
            for (int oo = 0; oo < 3; oo++) {
                float2 lo = unpack2(acc[2 * oo]);
                float2 hi = unpack2(acc[2 * oo + 1]);
                *(float4*)(U + (og * 3 + oo) * Rn + s2 * Tn + tg * 4) =
                    make_float4(lo.x, lo.y, hi.x, hi.y);
            }
        }
        __syncthreads();

        // ---- Wo (tensor) ----
        stageA<48, 36>(U, S, tid);
        __syncthreads();
        tmmC<48, HIDn, false>(S, woh, wol, bo_l, U + 5184, warp, lane);
        __syncthreads();

        layernorm2(h, U + 5184, g1_l, b1_l, tid);
        __syncthreads();

        // ---- ffn1 (tensor) ----
        stageA<48, 36>(h, S, tid);
        __syncthreads();
        tmmC<48, FFNn, true>(S, f1h, f1l, fb1_l, U, warp, lane);
        // ---- ffn2 (tensor, staged chunks; internal syncs; out -> S) ----
        tmm_ffn2(S, U, f2h, f2l, fb2_l, S, warp, lane, tid);
        __syncthreads();

        layernorm2(h, S, g2_l, b2_l, tid);
        __syncthreads();
    }

    // ---- fc + store ----
    if (tid < Rn) {
        int r = tid;
        int s2 = r / Tn, t = r % Tn;
        int n2 = nbase + s2;
        int b = n2 >> 9, c = n2 & (Cn - 1);
        float acc = __ldg(fcb);
        #pragma unroll
        for (int k = 0; k < HIDn; k++) acc = fmaf(h[k * Rn + r], __ldg(fcW + k), acc);
        out[(b * Tn + t) * Cn + c] = acc;
    }
}

// ---------------- launch ------------------------------------------------------
extern "C" void kernel_launch(void* const* d_in, const int* in_sizes, int n_in,
                              void* d_out, int out_size) {
    const float *pm, *ft, *W0, *W1, *cb, *tinW, *tinb, *Wq, *bq, *Wk, *bk,
                *Wv, *bv, *Wo, *bo, *g1, *b1, *fW1, *fb1, *fW2, *fb2,
                *g2, *b2, *fcW, *fcb;
    const int* ei;

    if (in_sizes[2] == 2 * EG) {
        pm  = (const float*)d_in[0];  ft  = (const float*)d_in[1];
        ei  = (const int*)  d_in[2];
        W0  = (const float*)d_in[3];  W1  = (const float*)d_in[4];
        cb  = (const float*)d_in[5];
        tinW= (const float*)d_in[6];  tinb= (const float*)d_in[7];
        Wq  = (const float*)d_in[8];  bq  = (const float*)d_in[9];
        Wk  = (const float*)d_in[10]; bk  = (const float*)d_in[11];
        Wv  = (const float*)d_in[12]; bv  = (const float*)d_in[13];
        Wo  = (const float*)d_in[14]; bo  = (const float*)d_in[15];
        g1  = (const float*)d_in[16]; b1  = (const float*)d_in[17];
        fW1 = (const float*)d_in[18]; fb1 = (const float*)d_in[19];
        fW2 = (const float*)d_in[20]; fb2 = (const float*)d_in[21];
        g2  = (const float*)d_in[22]; b2  = (const float*)d_in[23];
        fcW = (const float*)d_in[24]; fcb = (const float*)d_in[25];
    } else {
        pm  = (const float*)d_in[0];  ft  = (const float*)d_in[1];
        W0  = (const float*)d_in[2];  W1  = (const float*)d_in[3];
        cb  = (const float*)d_in[4];
        tinW= (const float*)d_in[5];  tinb= (const float*)d_in[6];
        Wq  = (const float*)d_in[7];  bq  = (const float*)d_in[8];
        Wk  = (const float*)d_in[9];  bk  = (const float*)d_in[10];
        Wv  = (const float*)d_in[11]; bv  = (const float*)d_in[12];
        Wo  = (const float*)d_in[13]; bo  = (const float*)d_in[14];
        g1  = (const float*)d_in[15]; b1  = (const float*)d_in[16];
        fW1 = (const float*)d_in[17]; fb1 = (const float*)d_in[18];
        fW2 = (const float*)d_in[19]; fb2 = (const float*)d_in[20];
        g2  = (const float*)d_in[21]; b2  = (const float*)d_in[22];
        fcW = (const float*)d_in[23]; fcb = (const float*)d_in[24];
        ei  = (const int*)  d_in[25];
    }

    k_count<<<Cn, 32>>>(ei);
    k_scan <<<1, Cn>>>();
    k_fill <<<Cn, 32>>>(ei);
    {
        int total = Nn * Tn * INF;
        k_pack<<<(total + 255) / 256, 256>>>(pm, ft);
    }
    k_wprep<<<(WB_TOT + 255) / 256, 256>>>(tinW, Wq, Wk, Wv, Wo, fW1, fW2);
    k_mega<<<Nn / SEQ, NT>>>(W0, W1, cb, tinb,
                             bq, bk, bv, bo, g1, b1, fb1, fb2, g2, b2,
                             fcW, fcb, (float*)d_out);
}

// round 14
// speedup vs baseline: 1.2069x; 1.0682x over previous
#include <cuda_runtime.h>
#include <cuda_bf16.h>
#include <math.h>
#include <stdint.h>

#define Bn   32
#define Tn   24
#define Cn   512
#define Nn   (Bn*Cn)
#define INF  14
#define HIDn 36
#define FFNn 144
#define HDn  18
#define EG   8192
#define SEQ  2
#define Rn   (SEQ*Tn)         // 48 rows per CTA
#define NT   128

// ---------------- scratch (device globals) -----------------------------------
__device__ float d_xn [Nn*Tn*INF];
__device__ float d_xn2[Nn*Tn*INF];
__device__ int   d_deg[Cn];
__device__ int   d_colcnt[Cn];
__device__ int   d_off[Cn+1];
__device__ float d_dinv[Cn];
__device__ int   d_brow[EG];
__device__ float d_bw[EG];
__device__ float d_pe[HIDn*Tn];

// bf16-split weights, [n][k] bf16x2 pairs (uint32), hi/lo planes.
// TIN [40][16]@0; QKVO 8x[40][24]@640; F1 2x[144][24]@8320; F2 2x[40][72]@15232
#define WB_TOT   20992
#define OFF_QKVO 640
#define OFF_F1   8320
#define OFF_F2   15232
__device__ uint32_t d_wbh[WB_TOT];
__device__ uint32_t d_wbl[WB_TOT];

// ---------------- K1 ----------------------------------------------------------
__global__ void k_count(const int* __restrict__ ei) {
    int c = blockIdx.x, lane = threadIdx.x;
    int cr = 0, cc = 0;
    for (int e = lane; e < EG; e += 32) {
        cr += (ei[e]      == c);
        cc += (ei[EG + e] == c);
    }
    #pragma unroll
    for (int o = 16; o; o >>= 1) {
        cr += __shfl_down_sync(0xffffffffu, cr, o);
        cc += __shfl_down_sync(0xffffffffu, cc, o);
    }
    if (lane == 0) { d_deg[c] = cr; d_colcnt[c] = cc; }
}

// ---------------- K2 ----------------------------------------------------------
__global__ void k_scan() {
    __shared__ int s[Cn];
    int t = threadIdx.x;
    s[t] = d_colcnt[t];
    __syncthreads();
    for (int o = 1; o < Cn; o <<= 1) {
        int v = (t >= o) ? s[t - o] : 0;
        __syncthreads();
        s[t] += v;
        __syncthreads();
    }
    d_off[t + 1] = s[t];
    if (t == 0) d_off[0] = 0;
    int dg = d_deg[t];
    d_dinv[t] = (dg > 0) ? (1.0f / sqrtf((float)dg)) : 0.0f;
    for (int i = t; i < HIDn * Tn; i += Cn) {
        int o = i / Tn, tt = i % Tn;
        float div = expf(-9.210340371976184f * (float)(o & ~1) / (float)HIDn);
        float ang = (float)tt * div;
        d_pe[i] = (o & 1) ? cosf(ang) : sinf(ang);
    }
}

// ---------------- K3 ----------------------------------------------------------
__global__ void k_fill(const int* __restrict__ ei) {
    int c = blockIdx.x, lane = threadIdx.x;
    int base = d_off[c];
    float dc = d_dinv[c];
    for (int e0 = 0; e0 < EG; e0 += 32) {
        int e = e0 + lane;
        int col = ei[EG + e];
        bool m = (col == c);
        unsigned mask = __ballot_sync(0xffffffffu, m);
        if (m) {
            int pos = base + __popc(mask & ((1u << lane) - 1u));
            int r = ei[e];
            d_brow[pos] = r;
            d_bw[pos]   = -(d_dinv[r] * dc);
        }
        base += __popc(mask);
    }
}

// ---------------- K4 ----------------------------------------------------------
__global__ void k_pack(const float* __restrict__ pm, const float* __restrict__ ft) {
    int idx = blockIdx.x * blockDim.x + threadIdx.x;
    if (idx >= Nn * Tn * INF) return;
    int f  = idx % INF;
    int rt = idx / INF;
    int t  = rt % Tn;
    int n  = rt / Tn;
    int b  = n >> 9, c = n & (Cn - 1);
    float v1, v2;
    if (f == 0) {
        v1 = pm[(b * Tn + t) * Cn + c];
        v2 = v1;
    } else {
        v1 = ft[((b * 2 * Tn + t)      * Cn + c) * 13 + (f - 1)];
        v2 = ft[((b * 2 * Tn + Tn + t) * Cn + c) * 13 + (f - 1)];
    }
    d_xn [idx] = v1;
    d_xn2[idx] = v2;
}

// ---------------- K5: weight bf16 hi/lo split ---------------------------------
__global__ void k_wprep(const float* __restrict__ tinW,
                        const float* __restrict__ Wq, const float* __restrict__ Wk,
                        const float* __restrict__ Wv, const float* __restrict__ Wo,
                        const float* __restrict__ fW1, const float* __restrict__ fW2) {
    int u = blockIdx.x * blockDim.x + threadIdx.x;
    if (u >= WB_TOT) return;
    float v0 = 0.0f, v1 = 0.0f;
    if (u < OFF_QKVO) {
        int n = u / 16, p = u % 16, k = 2 * p;
        if (n < 36) {
            if (k < 28)     v0 = tinW[k * 36 + n];
            if (k + 1 < 28) v1 = tinW[(k + 1) * 36 + n];
        }
    } else if (u < OFF_F1) {
        int q = u - OFF_QKVO;
        int mat = q / 960, r = q % 960;
        int l = mat >> 2, w = mat & 3;
        int n = r / 24, p = r % 24, k = 2 * p;
        const float* W = (w == 0 ? Wq : w == 1 ? Wk : w == 2 ? Wv : Wo) + l * 1296;
        if (n < 36) {
            if (k < 36)     v0 = W[k * 36 + n];
            if (k + 1 < 36) v1 = W[(k + 1) * 36 + n];
        }
    } else if (u < OFF_F2) {
        int q = u - OFF_F1;
        int l = q / 3456, r = q % 3456;
        int n = r / 24, p = r % 24, k = 2 * p;
        const float* W = fW1 + l * 5184;
        if (k < 36)     v0 = W[k * 144 + n];
        if (k + 1 < 36) v1 = W[(k + 1) * 144 + n];
    } else {
        int q = u - OFF_F2;
        int l = q / 2880, r = q % 2880;
        int n = r / 72, p = r % 72, k = 2 * p;
        const float* W = fW2 + l * 5184;
        if (n < 36) {
            v0 = W[k * 36 + n];
            v1 = W[(k + 1) * 36 + n];
        }
    }
    __nv_bfloat16 h0 = __float2bfloat16_rn(v0);
    __nv_bfloat16 h1 = __float2bfloat16_rn(v1);
    __nv_bfloat16 l0 = __float2bfloat16_rn(v0 - __bfloat162float(h0));
    __nv_bfloat16 l1 = __float2bfloat16_rn(v1 - __bfloat162float(h1));
    d_wbh[u] = (uint32_t)__bfloat16_as_ushort(h0) | ((uint32_t)__bfloat16_as_ushort(h1) << 16);
    d_wbl[u] = (uint32_t)__bfloat16_as_ushort(l0) | ((uint32_t)__bfloat16_as_ushort(l1) << 16);
}

// ---------------- bf16 helpers -------------------------------------------------
__device__ __forceinline__ void bfpair(float v0, float v1, uint32_t& hi, uint32_t& lo) {
    __nv_bfloat16 h0 = __float2bfloat16_rn(v0);
    __nv_bfloat16 h1 = __float2bfloat16_rn(v1);
    __nv_bfloat16 l0 = __float2bfloat16_rn(v0 - __bfloat162float(h0));
    __nv_bfloat16 l1 = __float2bfloat16_rn(v1 - __bfloat162float(h1));
    hi = (uint32_t)__bfloat16_as_ushort(h0) | ((uint32_t)__bfloat16_as_ushort(h1) << 16);
    lo = (uint32_t)__bfloat16_as_ushort(l0) | ((uint32_t)__bfloat16_as_ushort(l1) << 16);
}

template<int KP>
__device__ __forceinline__ int swzm(int m) {
    if (KP == 32) return ((((m >> 1) & 1) << 4) | (((m >> 2) & 1) << 5));
    return ((m >> 2) & 1) << 4;     // pitch 96B / 288B
}

// fp32 col-major [KD][48] -> staged row-major bf16 [48][KP] hi+lo (tin only)
template<int KP, int KD>
__device__ __forceinline__ void stageA(const float* __restrict__ IN, float* Sb, int tid) {
    uint32_t* H = reinterpret_cast<uint32_t*>(Sb);
    constexpr int PLANE = 48 * KP / 2;
    for (int u = tid; u < PLANE; u += NT) {
        int m = u % 48, p = u / 48;
        int k = 2 * p;
        float v0 = (k     < KD) ? IN[k * 48 + m]       : 0.0f;
        float v1 = (k + 1 < KD) ? IN[(k + 1) * 48 + m] : 0.0f;
        uint32_t hi, lo;
        bfpair(v0, v1, hi, lo);
        int idx = ((m * (KP * 2) + p * 4) ^ swzm<KP>(m)) >> 2;
        H[idx] = hi; H[PLANE + idx] = lo;
    }
}

__device__ __forceinline__ void ldm4(uint32_t& r0, uint32_t& r1, uint32_t& r2, uint32_t& r3,
                                     uint32_t addr) {
    asm volatile("ldmatrix.sync.aligned.m8n8.x4.shared.b16 {%0,%1,%2,%3}, [%4];"
                 : "=r"(r0), "=r"(r1), "=r"(r2), "=r"(r3) : "r"(addr));
}

__device__ __forceinline__ void mma_bf16(float& c0, float& c1, float& c2, float& c3,
                                         uint32_t a0, uint32_t a1, uint32_t a2, uint32_t a3,
                                         uint32_t b0, uint32_t b1) {
    asm volatile("mma.sync.aligned.m16n8k16.row.col.f32.bf16.bf16.f32 "
                 "{%0,%1,%2,%3}, {%4,%5,%6,%7}, {%8,%9}, {%0,%1,%2,%3};"
                 : "+f"(c0), "+f"(c1), "+f"(c2), "+f"(c3)
                 : "r"(a0), "r"(a1), "r"(a2), "r"(a3), "r"(b0), "r"(b1));
}

// OUT[NOUT][48] col-major fp32 = W^T @ staged-A (+bias)
template<int KP, int NOUT, bool RELU>
__device__ void tmmC(const float* Sb,
                     const uint32_t* __restrict__ wh, const uint32_t* __restrict__ wl,
                     const float* __restrict__ bias, float* __restrict__ OUT,
                     int warp, int lane) {
    constexpr int NTN = (NOUT + 7) / 8;
    constexpr int MYN = (NTN + 3) / 4;
    uint32_t sbase = (uint32_t)__cvta_generic_to_shared(Sb);
    int part = lane >> 3, rr = lane & 7;
    int g = lane >> 2, q2 = (lane & 3) * 2;
    #pragma unroll
    for (int mt = 0; mt < 3; mt++) {
        float C[MYN][4];
        #pragma unroll
        for (int i = 0; i < MYN; i++) { C[i][0]=0.f; C[i][1]=0.f; C[i][2]=0.f; C[i][3]=0.f; }
        #pragma unroll
        for (int kt = 0; kt < KP / 16; kt++) {
            int m = mt * 16 + rr + (part & 1) * 8;
            int colb = (kt * 16 + ((part >> 1) << 3)) * 2;
            uint32_t off = (uint32_t)((m * (KP * 2) + colb) ^ swzm<KP>(m));
            uint32_t ah0, ah1, ah2, ah3, al0, al1, al2, al3;
            ldm4(ah0, ah1, ah2, ah3, sbase + off);
            ldm4(al0, al1, al2, al3, sbase + 48 * KP * 2 + off);
            #pragma unroll
            for (int i = 0; i < MYN; i++) {
                int nt = warp + 4 * i;
                if (nt < NTN) {
                    int pi = (nt * 8 + g) * (KP / 2) + kt * 8 + (lane & 3);
                    uint32_t bh0 = __ldg(wh + pi), bh1 = __ldg(wh + pi + 4);
                    uint32_t bl0 = __ldg(wl + pi), bl1 = __ldg(wl + pi + 4);
                    mma_bf16(C[i][0], C[i][1], C[i][2], C[i][3], ah0, ah1, ah2, ah3, bh0, bh1);
                    mma_bf16(C[i][0], C[i][1], C[i][2], C[i][3], ah0, ah1, ah2, ah3, bl0, bl1);
                    mma_bf16(C[i][0], C[i][1], C[i][2], C[i][3], al0, al1, al2, al3, bh0, bh1);
                }
            }
        }
        #pragma unroll
        for (int i = 0; i < MYN; i++) {
            int nt = warp + 4 * i;
            if (nt < NTN) {
                int m = mt * 16 + g;
                int nA = nt * 8 + q2, nB = nA + 1;
                if ((NOUT & 7) == 0 || nA < NOUT) {
                    float bv = __ldg(bias + nA);
                    float a0 = C[i][0] + bv, a2 = C[i][2] + bv;
                    if (RELU) { a0 = fmaxf(a0, 0.f); a2 = fmaxf(a2, 0.f); }
                    OUT[nA * 48 + m] = a0; OUT[nA * 48 + m + 8] = a2;
                }
                if ((NOUT & 7) == 0 || nB < NOUT) {
                    float bv = __ldg(bias + nB);
                    float a1 = C[i][1] + bv, a3 = C[i][3] + bv;
                    if (RELU) { a1 = fmaxf(a1, 0.f); a3 = fmaxf(a3, 0.f); }
                    OUT[nB * 48 + m] = a1; OUT[nB * 48 + m + 8] = a3;
                }
            }
        }
    }
}

// ffn1: staged-A (KP=48) -> OUT staged bf16 [48][144] hi/lo in U (relu)
__device__ void tmmB(const float* Sb,
                     const uint32_t* __restrict__ wh, const uint32_t* __restrict__ wl,
                     const float* __restrict__ bias, float* __restrict__ OUTf,
                     int warp, int lane) {
    constexpr int NTN = 18;
    constexpr int MYN = 5;
    uint32_t sbase = (uint32_t)__cvta_generic_to_shared(Sb);
    uint32_t* OU = reinterpret_cast<uint32_t*>(OUTf);
    int part = lane >> 3, rr = lane & 7;
    int g = lane >> 2, q2 = (lane & 3) * 2;
    #pragma unroll
    for (int mt = 0; mt < 3; mt++) {
        float C[MYN][4];
        #pragma unroll
        for (int i = 0; i < MYN; i++) { C[i][0]=0.f; C[i][1]=0.f; C[i][2]=0.f; C[i][3]=0.f; }
        #pragma unroll
        for (int kt = 0; kt < 3; kt++) {
            int m = mt * 16 + rr + (part & 1) * 8;
            int colb = (kt * 16 + ((part >> 1) << 3)) * 2;
            uint32_t off = (uint32_t)((m * 96 + colb) ^ swzm<48>(m));
            uint32_t ah0, ah1, ah2, ah3, al0, al1, al2, al3;
            ldm4(ah0, ah1, ah2, ah3, sbase + off);
            ldm4(al0, al1, al2, al3, sbase + 4608 + off);
            #pragma unroll
            for (int i = 0; i < MYN; i++) {
                int nt = warp + 4 * i;
                if (nt < NTN) {
                    int pi = (nt * 8 + g) * 24 + kt * 8 + (lane & 3);
                    uint32_t bh0 = __ldg(wh + pi), bh1 = __ldg(wh + pi + 4);
                    uint32_t bl0 = __ldg(wl + pi), bl1 = __ldg(wl + pi + 4);
                    mma_bf16(C[i][0], C[i][1], C[i][2], C[i][3], ah0, ah1, ah2, ah3, bh0, bh1);
                    mma_bf16(C[i][0], C[i][1], C[i][2], C[i][3], ah0, ah1, ah2, ah3, bl0, bl1);
                    mma_bf16(C[i][0], C[i][1], C[i][2], C[i][3], al0, al1, al2, al3, bh0, bh1);
                }
            }
        }
        #pragma unroll
        for (int i = 0; i < MYN; i++) {
            int nt = warp + 4 * i;
            if (nt < NTN) {
                int m = mt * 16 + g;
                int nA = nt * 8 + q2;
                float bv0 = __ldg(bias + nA), bv1 = __ldg(bias + nA + 1);
                float a0 = fmaxf(C[i][0] + bv0, 0.f), a1 = fmaxf(C[i][1] + bv1, 0.f);
                float a2 = fmaxf(C[i][2] + bv0, 0.f), a3 = fmaxf(C[i][3] + bv1, 0.f);
                int pidx = nt * 4 + (lane & 3);
                uint32_t hi, lo;
                bfpair(a0, a1, hi, lo);
                int b0 = (m * 288 + pidx * 4) ^ swzm<144>(m);
                OU[b0 >> 2] = hi; OU[3456 + (b0 >> 2)] = lo;
                bfpair(a2, a3, hi, lo);
                int b1 = ((m + 8) * 288 + pidx * 4) ^ swzm<144>(m + 8);
                OU[b1 >> 2] = hi; OU[3456 + (b1 >> 2)] = lo;
            }
        }
    }
}

// ---------------- scalar helpers ----------------------------------------------
__device__ __forceinline__ uint64_t pack2(float v) {
    uint64_t r;
    asm("mov.b64 %0, {%1, %1};" : "=l"(r) : "f"(v));
    return r;
}
__device__ __forceinline__ void fma2(uint64_t& acc, uint64_t a, uint64_t b) {
    asm("fma.rn.f32x2 %0, %1, %2, %0;" : "+l"(acc) : "l"(a), "l"(b));
}
__device__ __forceinline__ float2 unpack2(uint64_t v) {
    float lo, hi;
    asm("mov.b64 {%0, %1}, %2;" : "=f"(lo), "=f"(hi) : "l"(v));
    return make_float2(lo, hi);
}

// LN + staged emit, ALIAS-SAFE: res reads complete (barrier) before Sst writes.
// NOT inside divergent control flow — all threads reach the internal barrier.
__device__ __forceinline__ void layernorm2s(float* __restrict__ h,
                                            const float* __restrict__ res,
                                            const float* __restrict__ g,
                                            const float* __restrict__ bb,
                                            float* __restrict__ Sst, int tid) {
    uint32_t* SU = reinterpret_cast<uint32_t*>(Sst);
    int r = tid >> 1, half = tid & 1;
    float vloc[18];
    float m = 0.0f, rs = 0.0f;
    if (tid < 96) {
        float q2 = 0.0f;
        #pragma unroll
        for (int kk = 0; kk < 18; kk++) {
            int k = half * 18 + kk;
            float v = h[k * Rn + r] + res[k * Rn + r];
            vloc[kk] = v;
            m += v; q2 += v * v;
        }
        m  += __shfl_xor_sync(0xffffffffu, m, 1);
        q2 += __shfl_xor_sync(0xffffffffu, q2, 1);
        m *= (1.0f / HIDn);
        float var = q2 * (1.0f / HIDn) - m * m;
        rs = rsqrtf(var + 1e-5f);
    }
    __syncthreads();   // all res reads done before any (possibly aliased) Sst write
    if (tid < 96) {
        #pragma unroll
        for (int i = 0; i < 9; i++) {
            int k = half * 18 + 2 * i;
            float v0 = (vloc[2 * i]     - m) * rs * __ldg(g + k)     + __ldg(bb + k);
            float v1 = (vloc[2 * i + 1] - m) * rs * __ldg(g + k + 1) + __ldg(bb + k + 1);
            h[k * Rn + r] = v0;
            h[(k + 1) * Rn + r] = v1;
            uint32_t hi, lo;
            bfpair(v0, v1, hi, lo);
            int p = half * 9 + i;
            int byte = (r * 96 + p * 4) ^ swzm<48>(r);
            SU[byte >> 2] = hi; SU[1152 + (byte >> 2)] = lo;
        }
    }
    // zero pads (pairs 18..23) — post-barrier, safe vs aliased res
    for (int u = tid; u < 288; u += NT) {
        int rr2 = u % 48, p = 18 + u / 48;
        int byte = (rr2 * 96 + p * 4) ^ swzm<48>(rr2);
        SU[byte >> 2] = 0; SU[1152 + (byte >> 2)] = 0;
    }
}

// ---------------- K6: mega-kernel ---------------------------------------------
__global__ __launch_bounds__(NT, 5)
void k_mega(const float* __restrict__ W0,  const float* __restrict__ W1,
            const float* __restrict__ cb,  const float* __restrict__ tinb,
            const float* __restrict__ bq,  const float* __restrict__ bk,
            const float* __restrict__ bv,  const float* __restrict__ bo,
            const float* __restrict__ g1,  const float* __restrict__ b1,
            const float* __restrict__ fb1, const float* __restrict__ fb2,
            const float* __restrict__ g2,  const float* __restrict__ b2,
            const float* __restrict__ fcW, const float* __restrict__ fcb,
            float* __restrict__ out) {
    __shared__ __align__(16) float sh_h[HIDn * Rn];     // 1728
    __shared__ __align__(16) float sh_U[FFNn * Rn];     // 6912 (27648 B)
    __shared__ __align__(16) float sh_S[2304];          // 9216 B

    float* h = sh_h;
    float* U = sh_U;
    float* S = sh_S;
    float* x   = U;
    float* tx  = U + 672;
    float* cat = U + 1344;

    const int tid = threadIdx.x;
    const int warp = tid >> 5, lane = tid & 31;
    const int nbase = blockIdx.x * SEQ;

    // ---- stage self tiles ----
    for (int idx = tid; idx < SEQ * Tn * INF; idx += NT) {
        int s2 = idx / 336, u = idx % 336;
        int t = u / INF, f = u % INF;
        int n2 = nbase + s2;
        x  [f * Rn + s2 * Tn + t] = d_xn [n2 * 336 + u];
        cat[f * Rn + s2 * Tn + t] = d_xn2[n2 * 336 + u];
    }

    // ---- ChebConv gather ----
    {
        int s2 = tid >> 6, l = tid & 63;
        int n2 = nbase + s2;
        int b = n2 >> 9, c = n2 & (Cn - 1);
        float acc[6];
        #pragma unroll
        for (int i = 0; i < 6; i++) acc[i] = 0.0f;
        int start = d_off[c], end = d_off[c + 1];
        for (int e = start; e < end; e++) {
            int   rr = __ldg(d_brow + e);
            float w  = __ldg(d_bw + e);
            const float* nb = d_xn + (b * Cn + rr) * 336;
            #pragma unroll
            for (int i = 0; i < 6; i++) {
                int u = l + i * 64;
                if (u < 336) acc[i] = fmaf(w, nb[u], acc[i]);
            }
        }
        #pragma unroll
        for (int i = 0; i < 6; i++) {
            int u = l + i * 64;
            if (u < 336) {
                int t = u / INF, f = u % INF;
                tx[f * Rn + s2 * Tn + t] = acc[i];
            }
        }
    }
    __syncthreads();

    // ---- gate ----
    for (int idx = tid; idx < Rn * INF; idx += NT) {
        int r = idx % Rn, j = idx / Rn;
        float sacc = __ldg(cb + j);
        #pragma unroll
        for (int f = 0; f < INF; f++) {
            sacc = fmaf(x [f * Rn + r], __ldg(W0 + f * INF + j), sacc);
            sacc = fmaf(tx[f * Rn + r], __ldg(W1 + f * INF + j), sacc);
        }
        cat[(INF + j) * Rn + r] = __fdividef(1.0f, 1.0f + __expf(-sacc));
    }
    __syncthreads();

    // ---- tin (tensor) ----
    stageA<32, 28>(cat, S, tid);
    __syncthreads();
    tmmC<32, HIDn, false>(S, d_wbh, d_wbl, tinb, h, warp, lane);
    __syncthreads();

    // ---- PE + staged-h emit into S ----
    {
        uint32_t* SU = reinterpret_cast<uint32_t*>(S);
        for (int u = tid; u < 48 * 18; u += NT) {
            int r = u % 48, p = u / 48;
            int k = 2 * p, t = r % Tn;
            float v0 = h[k * Rn + r]       + __ldg(d_pe + k * Tn + t);
            float v1 = h[(k + 1) * Rn + r] + __ldg(d_pe + (k + 1) * Tn + t);
            h[k * Rn + r] = v0;
            h[(k + 1) * Rn + r] = v1;
            uint32_t hi, lo;
            bfpair(v0, v1, hi, lo);
            int byte = (r * 96 + p * 4) ^ swzm<48>(r);
            SU[byte >> 2] = hi; SU[1152 + (byte >> 2)] = lo;
        }
        for (int u = tid; u < 288; u += NT) {
            int r = u % 48, p = 18 + u / 48;
            int byte = (r * 96 + p * 4) ^ swzm<48>(r);
            SU[byte >> 2] = 0; SU[1152 + (byte >> 2)] = 0;
        }
    }
    __syncthreads();

    const float scale = 0.23570226039551584f;
    #pragma unroll 1
    for (int l = 0; l < 2; l++) {
        const uint32_t* wqh = d_wbh + OFF_QKVO + (l * 4 + 0) * 960;
        const uint32_t* wkh = d_wbh + OFF_QKVO + (l * 4 + 1) * 960;
        const uint32_t* wvh = d_wbh + OFF_QKVO + (l * 4 + 2) * 960;
        const uint32_t* woh = d_wbh + OFF_QKVO + (l * 4 + 3) * 960;
        const uint32_t* wql = d_wbl + OFF_QKVO + (l * 4 + 0) * 960;
        const uint32_t* wkl = d_wbl + OFF_QKVO + (l * 4 + 1) * 960;
        const uint32_t* wvl = d_wbl + OFF_QKVO + (l * 4 + 2) * 960;
        const uint32_t* wol = d_wbl + OFF_QKVO + (l * 4 + 3) * 960;
        const uint32_t* f1h = d_wbh + OFF_F1 + l * 3456;
        const uint32_t* f1l = d_wbl + OFF_F1 + l * 3456;
        const uint32_t* f2h = d_wbh + OFF_F2 + l * 2880;
        const uint32_t* f2l = d_wbl + OFF_F2 + l * 2880;
        const float* bq_l = bq + l * HIDn;  const float* bk_l = bk + l * HIDn;
        const float* bv_l = bv + l * HIDn;  const float* bo_l = bo + l * HIDn;
        const float* g1_l = g1 + l * HIDn;  const float* b1_l = b1 + l * HIDn;
        const float* g2_l = g2 + l * HIDn;  const float* b2_l = b2 + l * HIDn;
        const float* fb1_l = fb1 + l * FFNn; const float* fb2_l = fb2 + l * HIDn;

        // ---- q,k,v from staged S ----
        tmmC<48, HIDn, false>(S, wqh, wql, bq_l, U,        warp, lane);
        tmmC<48, HIDn, false>(S, wkh, wkl, bk_l, U + 1728, warp, lane);
        tmmC<48, HIDn, false>(S, wvh, wvl, bv_l, U + 3456, warp, lane);
        __syncthreads();

        // ---- scores (overwrite S) ----
        for (int tile = tid; tile < 144; tile += NT) {
            int bs = tile / 36, rem = tile % 36;
            int ig = rem % 6, jg = rem / 6;
            int s2 = bs >> 1, hh = bs & 1;
            const float* qb = U        + hh * HDn * Rn + s2 * Tn + ig * 4;
            const float* kb = U + 1728 + hh * HDn * Rn + s2 * Tn + jg * 4;
            uint64_t acc[8];
            #pragma unroll
            for (int i = 0; i < 8; i++) acc[i] = 0ull;
            #pragma unroll 2
            for (int d = 0; d < HDn; d++) {
                ulonglong2 qv = *(const ulonglong2*)(qb + d * Rn);
                float4 kv = *(const float4*)(kb + d * Rn);
                uint64_t k0 = pack2(kv.x), k1 = pack2(kv.y), k2 = pack2(kv.z), k3 = pack2(kv.w);
                fma2(acc[0], qv.x, k0); fma2(acc[1], qv.y, k0);
                fma2(acc[2], qv.x, k1); fma2(acc[3], qv.y, k1);
                fma2(acc[4], qv.x, k2); fma2(acc[5], qv.y, k2);
                fma2(acc[6], qv.x, k3); fma2(acc[7], qv.y, k3);
            }
            int rowbase = s2 * 48 + hh * 24 + ig * 4;
            #pragma unroll
            for (int jj = 0; jj < 4; jj++) {
                float2 lo = unpack2(acc[2 * jj]);
                float2 hi = unpack2(acc[2 * jj + 1]);
                *(float4*)(S + (jg * 4 + jj) * 96 + rowbase) =
                    make_float4(lo.x * scale, lo.y * scale, hi.x * scale, hi.y * scale);
            }
        }
        __syncthreads();

        // softmax
        if (tid < 96) {
            float m = S[tid];
            #pragma unroll
            for (int j = 1; j < Tn; j++) m = fmaxf(m, S[j * 96 + tid]);
            float sum = 0.0f;
            #pragma unroll
            for (int j = 0; j < Tn; j++) {
                float e = __expf(S[j * 96 + tid] - m);
                S[j * 96 + tid] = e;
                sum += e;
            }
            float inv = __fdividef(1.0f, sum);
            #pragma unroll
            for (int j = 0; j < Tn; j++) S[j * 96 + tid] *= inv;
        }
        __syncthreads();

        // ---- attn out: staged bf16 [48][48] into U[0..2304) (q/k space, dead) ----
        {
            uint32_t* UU = reinterpret_cast<uint32_t*>(U);
            for (int tile = tid; tile < 216; tile += NT) {
                int s2 = tile / 108, rem = tile % 108;
                int og = rem / 6, tg = rem % 6;
                int o0 = og * 2, hh = o0 / HDn;
                const float* ab = S + s2 * 48 + hh * 24 + tg * 4;
                const float* vb = U + 3456 + o0 * Rn + s2 * Tn;
                uint64_t acc[4];
                #pragma unroll
                for (int i = 0; i < 4; i++) acc[i] = 0ull;
                #pragma unroll 4
                for (int j = 0; j < Tn; j++) {
                    ulonglong2 avv = *(const ulonglong2*)(ab + j * 96);
                    uint64_t p0 = pack2(vb[j]);
                    uint64_t p1 = pack2(vb[Rn + j]);
                    fma2(acc[0], avv.x, p0); fma2(acc[1], avv.y, p0);
                    fma2(acc[2], avv.x, p1); fma2(acc[3], avv.y, p1);
                }
                float2 a0 = unpack2(acc[0]), a1 = unpack2(acc[1]);
                float2 a2 = unpack2(acc[2]), a3 = unpack2(acc[3]);
                float v0s[4] = {a0.x, a0.y, a1.x, a1.y};
                float v1s[4] = {a2.x, a2.y, a3.x, a3.y};
                #pragma unroll
                for (int rr = 0; rr < 4; rr++) {
                    int m = s2 * Tn + tg * 4 + rr;
                    uint32_t hi, lo;
                    bfpair(v0s[rr], v1s[rr], hi, lo);
                    int byte = (m * 96 + og * 4) ^ swzm<48>(m);
                    UU[byte >> 2] = hi; UU[1152 + (byte >> 2)] = lo;
                }
            }
            for (int u = tid; u < 288; u += NT) {
                int r = u % 48, p = 18 + u / 48;
                int byte = (r * 96 + p * 4) ^ swzm<48>(r);
                UU[byte >> 2] = 0; UU[1152 + (byte >> 2)] = 0;
            }
        }
        __syncthreads();

        // ---- Wo (tensor): staged U -> fp32 U+5184 ----
        tmmC<48, HIDn, false>(U, woh, wol, bo_l, U + 5184, warp, lane);
        __syncthreads();

        // ---- LN1 -> h fp32 + staged S ----
        layernorm2s(h, U + 5184, g1_l, b1_l, S, tid);
        __syncthreads();

        // ---- ffn1: staged S -> staged bf16 U (relu) ----
        tmmB(S, f1h, f1l, fb1_l, U, warp, lane);
        __syncthreads();

        // ---- ffn2: staged U (KP=144) -> fp32 S ----
        tmmC<144, HIDn, false>(U, f2h, f2l, fb2_l, S, warp, lane);
        __syncthreads();

        // ---- LN2 -> h fp32 + staged S; res ALIASES Sst (handled inside) ----
        layernorm2s(h, S, g2_l, b2_l, S, tid);
        __syncthreads();
    }

    // ---- fc + store ----
    if (tid < Rn) {
        int r = tid;
        int s2 = r / Tn, t = r % Tn;
        int n2 = nbase + s2;
        int b = n2 >> 9, c = n2 & (Cn - 1);
        float acc = __ldg(fcb);
        #pragma unroll
        for (int k = 0; k < HIDn; k++) acc = fmaf(h[k * Rn + r], __ldg(fcW + k), acc);
        out[(b * Tn + t) * Cn + c] = acc;
    }
}

// ---------------- launch ------------------------------------------------------
extern "C" void kernel_launch(void* const* d_in, const int* in_sizes, int n_in,
                              void* d_out, int out_size) {
    const float *pm, *ft, *W0, *W1, *cb, *tinW, *tinb, *Wq, *bq, *Wk, *bk,
                *Wv, *bv, *Wo, *bo, *g1, *b1, *fW1, *fb1, *fW2, *fb2,
                *g2, *b2, *fcW, *fcb;
    const int* ei;

    if (in_sizes[2] == 2 * EG) {
        pm  = (const float*)d_in[0];  ft  = (const float*)d_in[1];
        ei  = (const int*)  d_in[2];
        W0  = (const float*)d_in[3];  W1  = (const float*)d_in[4];
        cb  = (const float*)d_in[5];
        tinW= (const float*)d_in[6];  tinb= (const float*)d_in[7];
        Wq  = (const float*)d_in[8];  bq  = (const float*)d_in[9];
        Wk  = (const float*)d_in[10]; bk  = (const float*)d_in[11];
        Wv  = (const float*)d_in[12]; bv  = (const float*)d_in[13];
        Wo  = (const float*)d_in[14]; bo  = (const float*)d_in[15];
        g1  = (const float*)d_in[16]; b1  = (const float*)d_in[17];
        fW1 = (const float*)d_in[18]; fb1 = (const float*)d_in[19];
        fW2 = (const float*)d_in[20]; fb2 = (const float*)d_in[21];
        g2  = (const float*)d_in[22]; b2  = (const float*)d_in[23];
        fcW = (const float*)d_in[24]; fcb = (const float*)d_in[25];
    } else {
        pm  = (const float*)d_in[0];  ft  = (const float*)d_in[1];
        W0  = (const float*)d_in[2];  W1  = (const float*)d_in[3];
        cb  = (const float*)d_in[4];
        tinW= (const float*)d_in[5];  tinb= (const float*)d_in[6];
        Wq  = (const float*)d_in[7];  bq  = (const float*)d_in[8];
        Wk  = (const float*)d_in[9];  bk  = (const float*)d_in[10];
        Wv  = (const float*)d_in[11]; bv  = (const float*)d_in[12];
        Wo  = (const float*)d_in[13]; bo  = (const float*)d_in[14];
        g1  = (const float*)d_in[15]; b1  = (const float*)d_in[16];
        fW1 = (const float*)d_in[17]; fb1 = (const float*)d_in[18];
        fW2 = (const float*)d_in[19]; fb2 = (const float*)d_in[20];
        g2  = (const float*)d_in[21]; b2  = (const float*)d_in[22];
        fcW = (const float*)d_in[23]; fcb = (const float*)d_in[24];
        ei  = (const int*)  d_in[25];
    }

    k_count<<<Cn, 32>>>(ei);
    k_scan <<<1, Cn>>>();
    k_fill <<<Cn, 32>>>(ei);
    {
        int total = Nn * Tn * INF;
        k_pack<<<(total + 255) / 256, 256>>>(pm, ft);
    }
    k_wprep<<<(WB_TOT + 255) / 256, 256>>>(tinW, Wq, Wk, Wv, Wo, fW1, fW2);
    k_mega<<<Nn / SEQ, NT>>>(W0, W1, cb, tinb,
                             bq, bk, bv, bo, g1, b1, fb1, fb2, g2, b2,
                             fcW, fcb, (float*)d_out);
}

// round 16
// speedup vs baseline: 1.2274x; 1.0170x over previous
#include <cuda_runtime.h>
#include <cuda_bf16.h>
#include <math.h>
#include <stdint.h>

#define Bn   32
#define Tn   24
#define Cn   512
#define Nn   (Bn*Cn)
#define INF  14
#define HIDn 36
#define FFNn 144
#define HDn  18
#define EG   8192
#define SEQ  2
#define Rn   (SEQ*Tn)         // 48 rows per CTA
#define NT   128

// ---------------- scratch (device globals) -----------------------------------
__device__ float d_xn [Nn*Tn*INF];
__device__ float d_xn2[Nn*Tn*INF];
__device__ int   d_deg[Cn];
__device__ int   d_colcnt[Cn];
__device__ int   d_off[Cn+1];
__device__ float d_dinv[Cn];
__device__ int   d_brow[EG];
__device__ float d_bw[EG];
__device__ float d_pe[HIDn*Tn];

// bf16-split weights, [n][k] bf16x2 pairs (uint32), hi/lo planes.
// TIN [40][16]@0; QKVO 8x[40][24]@640; F1 2x[144][24]@8320; F2 2x[40][72]@15232
#define WB_TOT   20992
#define OFF_QKVO 640
#define OFF_F1   8320
#define OFF_F2   15232
__device__ uint32_t d_wbh[WB_TOT];
__device__ uint32_t d_wbl[WB_TOT];

// ---------------- K1 ----------------------------------------------------------
__global__ void k_count(const int* __restrict__ ei) {
    int c = blockIdx.x, lane = threadIdx.x;
    int cr = 0, cc = 0;
    for (int e = lane; e < EG; e += 32) {
        cr += (ei[e]      == c);
        cc += (ei[EG + e] == c);
    }
    #pragma unroll
    for (int o = 16; o; o >>= 1) {
        cr += __shfl_down_sync(0xffffffffu, cr, o);
        cc += __shfl_down_sync(0xffffffffu, cc, o);
    }
    if (lane == 0) { d_deg[c] = cr; d_colcnt[c] = cc; }
}

// ---------------- K2 ----------------------------------------------------------
__global__ void k_scan() {
    __shared__ int s[Cn];
    int t = threadIdx.x;
    s[t] = d_colcnt[t];
    __syncthreads();
    for (int o = 1; o < Cn; o <<= 1) {
        int v = (t >= o) ? s[t - o] : 0;
        __syncthreads();
        s[t] += v;
        __syncthreads();
    }
    d_off[t + 1] = s[t];
    if (t == 0) d_off[0] = 0;
    int dg = d_deg[t];
    d_dinv[t] = (dg > 0) ? (1.0f / sqrtf((float)dg)) : 0.0f;
    for (int i = t; i < HIDn * Tn; i += Cn) {
        int o = i / Tn, tt = i % Tn;
        float div = expf(-9.210340371976184f * (float)(o & ~1) / (float)HIDn);
        float ang = (float)tt * div;
        d_pe[i] = (o & 1) ? cosf(ang) : sinf(ang);
    }
}

// ---------------- K3 ----------------------------------------------------------
__global__ void k_fill(const int* __restrict__ ei) {
    int c = blockIdx.x, lane = threadIdx.x;
    int base = d_off[c];
    float dc = d_dinv[c];
    for (int e0 = 0; e0 < EG; e0 += 32) {
        int e = e0 + lane;
        int col = ei[EG + e];
        bool m = (col == c);
        unsigned mask = __ballot_sync(0xffffffffu, m);
        if (m) {
            int pos = base + __popc(mask & ((1u << lane) - 1u));
            int r = ei[e];
            d_brow[pos] = r;
            d_bw[pos]   = -(d_dinv[r] * dc);
        }
        base += __popc(mask);
    }
}

// ---------------- K4 ----------------------------------------------------------
__global__ void k_pack(const float* __restrict__ pm, const float* __restrict__ ft) {
    int idx = blockIdx.x * blockDim.x + threadIdx.x;
    if (idx >= Nn * Tn * INF) return;
    int f  = idx % INF;
    int rt = idx / INF;
    int t  = rt % Tn;
    int n  = rt / Tn;
    int b  = n >> 9, c = n & (Cn - 1);
    float v1, v2;
    if (f == 0) {
        v1 = pm[(b * Tn + t) * Cn + c];
        v2 = v1;
    } else {
        v1 = ft[((b * 2 * Tn + t)      * Cn + c) * 13 + (f - 1)];
        v2 = ft[((b * 2 * Tn + Tn + t) * Cn + c) * 13 + (f - 1)];
    }
    d_xn [idx] = v1;
    d_xn2[idx] = v2;
}

// ---------------- K5: weight bf16 hi/lo split ---------------------------------
__global__ void k_wprep(const float* __restrict__ tinW,
                        const float* __restrict__ Wq, const float* __restrict__ Wk,
                        const float* __restrict__ Wv, const float* __restrict__ Wo,
                        const float* __restrict__ fW1, const float* __restrict__ fW2) {
    int u = blockIdx.x * blockDim.x + threadIdx.x;
    if (u >= WB_TOT) return;
    float v0 = 0.0f, v1 = 0.0f;
    if (u < OFF_QKVO) {
        int n = u / 16, p = u % 16, k = 2 * p;
        if (n < 36) {
            if (k < 28)     v0 = tinW[k * 36 + n];
            if (k + 1 < 28) v1 = tinW[(k + 1) * 36 + n];
        }
    } else if (u < OFF_F1) {
        int q = u - OFF_QKVO;
        int mat = q / 960, r = q % 960;
        int l = mat >> 2, w = mat & 3;
        int n = r / 24, p = r % 24, k = 2 * p;
        const float* W = (w == 0 ? Wq : w == 1 ? Wk : w == 2 ? Wv : Wo) + l * 1296;
        if (n < 36) {
            if (k < 36)     v0 = W[k * 36 + n];
            if (k + 1 < 36) v1 = W[(k + 1) * 36 + n];
        }
    } else if (u < OFF_F2) {
        int q = u - OFF_F1;
        int l = q / 3456, r = q % 3456;
        int n = r / 24, p = r % 24, k = 2 * p;
        const float* W = fW1 + l * 5184;
        if (k < 36)     v0 = W[k * 144 + n];
        if (k + 1 < 36) v1 = W[(k + 1) * 144 + n];
    } else {
        int q = u - OFF_F2;
        int l = q / 2880, r = q % 2880;
        int n = r / 72, p = r % 72, k = 2 * p;
        const float* W = fW2 + l * 5184;
        if (n < 36) {
            v0 = W[k * 36 + n];
            v1 = W[(k + 1) * 36 + n];
        }
    }
    __nv_bfloat16 h0 = __float2bfloat16_rn(v0);
    __nv_bfloat16 h1 = __float2bfloat16_rn(v1);
    __nv_bfloat16 l0 = __float2bfloat16_rn(v0 - __bfloat162float(h0));
    __nv_bfloat16 l1 = __float2bfloat16_rn(v1 - __bfloat162float(h1));
    d_wbh[u] = (uint32_t)__bfloat16_as_ushort(h0) | ((uint32_t)__bfloat16_as_ushort(h1) << 16);
    d_wbl[u] = (uint32_t)__bfloat16_as_ushort(l0) | ((uint32_t)__bfloat16_as_ushort(l1) << 16);
}

// ---------------- bf16 helpers -------------------------------------------------
__device__ __forceinline__ void bfpair(float v0, float v1, uint32_t& hi, uint32_t& lo) {
    __nv_bfloat16 h0 = __float2bfloat16_rn(v0);
    __nv_bfloat16 h1 = __float2bfloat16_rn(v1);
    __nv_bfloat16 l0 = __float2bfloat16_rn(v0 - __bfloat162float(h0));
    __nv_bfloat16 l1 = __float2bfloat16_rn(v1 - __bfloat162float(h1));
    hi = (uint32_t)__bfloat16_as_ushort(h0) | ((uint32_t)__bfloat16_as_ushort(h1) << 16);
    lo = (uint32_t)__bfloat16_as_ushort(l0) | ((uint32_t)__bfloat16_as_ushort(l1) << 16);
}

template<int KP>
__device__ __forceinline__ int swzm(int m) {
    if (KP == 32) return ((((m >> 1) & 1) << 4) | (((m >> 2) & 1) << 5));
    return ((m >> 2) & 1) << 4;     // pitch 96B / 288B
}

// fp32 col-major [KD][48] -> staged row-major bf16 [48][KP] hi+lo (tin only)
template<int KP, int KD>
__device__ __forceinline__ void stageA(const float* __restrict__ IN, float* Sb, int tid) {
    uint32_t* H = reinterpret_cast<uint32_t*>(Sb);
    constexpr int PLANE = 48 * KP / 2;
    for (int u = tid; u < PLANE; u += NT) {
        int m = u % 48, p = u / 48;
        int k = 2 * p;
        float v0 = (k     < KD) ? IN[k * 48 + m]       : 0.0f;
        float v1 = (k + 1 < KD) ? IN[(k + 1) * 48 + m] : 0.0f;
        uint32_t hi, lo;
        bfpair(v0, v1, hi, lo);
        int idx = ((m * (KP * 2) + p * 4) ^ swzm<KP>(m)) >> 2;
        H[idx] = hi; H[PLANE + idx] = lo;
    }
}

__device__ __forceinline__ void ldm4(uint32_t& r0, uint32_t& r1, uint32_t& r2, uint32_t& r3,
                                     uint32_t addr) {
    asm volatile("ldmatrix.sync.aligned.m8n8.x4.shared.b16 {%0,%1,%2,%3}, [%4];"
                 : "=r"(r0), "=r"(r1), "=r"(r2), "=r"(r3) : "r"(addr));
}

__device__ __forceinline__ void mma_bf16(float& c0, float& c1, float& c2, float& c3,
                                         uint32_t a0, uint32_t a1, uint32_t a2, uint32_t a3,
                                         uint32_t b0, uint32_t b1) {
    asm volatile("mma.sync.aligned.m16n8k16.row.col.f32.bf16.bf16.f32 "
                 "{%0,%1,%2,%3}, {%4,%5,%6,%7}, {%8,%9}, {%0,%1,%2,%3};"
                 : "+f"(c0), "+f"(c1), "+f"(c2), "+f"(c3)
                 : "r"(a0), "r"(a1), "r"(a2), "r"(a3), "r"(b0), "r"(b1));
}

// OUT[NOUT][48] col-major fp32 = W^T @ staged-A (+bias).
// HOIST: preload weight fragments once (indep of mt). Use only when MYN<=2, KP<=48.
template<int KP, int NOUT, bool RELU, bool HOIST>
__device__ void tmmC(const float* Sb,
                     const uint32_t* __restrict__ wh, const uint32_t* __restrict__ wl,
                     const float* __restrict__ bias, float* __restrict__ OUT,
                     int warp, int lane) {
    constexpr int NTN = (NOUT + 7) / 8;
    constexpr int MYN = (NTN + 3) / 4;
    constexpr int NKT = KP / 16;
    uint32_t sbase = (uint32_t)__cvta_generic_to_shared(Sb);
    int part = lane >> 3, rr = lane & 7;
    int g = lane >> 2, q2 = (lane & 3) * 2;

    uint32_t wr[HOIST ? MYN : 1][HOIST ? NKT : 1][4];
    if (HOIST) {
        #pragma unroll
        for (int i = 0; i < MYN; i++) {
            int nt = warp + 4 * i;
            #pragma unroll
            for (int kt = 0; kt < NKT; kt++) {
                if (nt < NTN) {
                    int pi = (nt * 8 + g) * (KP / 2) + kt * 8 + (lane & 3);
                    wr[i][kt][0] = __ldg(wh + pi); wr[i][kt][1] = __ldg(wh + pi + 4);
                    wr[i][kt][2] = __ldg(wl + pi); wr[i][kt][3] = __ldg(wl + pi + 4);
                } else {
                    wr[i][kt][0] = wr[i][kt][1] = wr[i][kt][2] = wr[i][kt][3] = 0u;
                }
            }
        }
    }

    #pragma unroll
    for (int mt = 0; mt < 3; mt++) {
        float C[MYN][4];
        #pragma unroll
        for (int i = 0; i < MYN; i++) { C[i][0]=0.f; C[i][1]=0.f; C[i][2]=0.f; C[i][3]=0.f; }
        #pragma unroll
        for (int kt = 0; kt < NKT; kt++) {
            int m = mt * 16 + rr + (part & 1) * 8;
            int colb = (kt * 16 + ((part >> 1) << 3)) * 2;
            uint32_t off = (uint32_t)((m * (KP * 2) + colb) ^ swzm<KP>(m));
            uint32_t ah0, ah1, ah2, ah3, al0, al1, al2, al3;
            ldm4(ah0, ah1, ah2, ah3, sbase + off);
            ldm4(al0, al1, al2, al3, sbase + 48 * KP * 2 + off);
            #pragma unroll
            for (int i = 0; i < MYN; i++) {
                int nt = warp + 4 * i;
                if (nt < NTN) {
                    uint32_t bh0, bh1, bl0, bl1;
                    if (HOIST) {
                        bh0 = wr[i][kt][0]; bh1 = wr[i][kt][1];
                        bl0 = wr[i][kt][2]; bl1 = wr[i][kt][3];
                    } else {
                        int pi = (nt * 8 + g) * (KP / 2) + kt * 8 + (lane & 3);
                        bh0 = __ldg(wh + pi); bh1 = __ldg(wh + pi + 4);
                        bl0 = __ldg(wl + pi); bl1 = __ldg(wl + pi + 4);
                    }
                    mma_bf16(C[i][0], C[i][1], C[i][2], C[i][3], ah0, ah1, ah2, ah3, bh0, bh1);
                    mma_bf16(C[i][0], C[i][1], C[i][2], C[i][3], ah0, ah1, ah2, ah3, bl0, bl1);
                    mma_bf16(C[i][0], C[i][1], C[i][2], C[i][3], al0, al1, al2, al3, bh0, bh1);
                }
            }
        }
        #pragma unroll
        for (int i = 0; i < MYN; i++) {
            int nt = warp + 4 * i;
            if (nt < NTN) {
                int m = mt * 16 + g;
                int nA = nt * 8 + q2, nB = nA + 1;
                if ((NOUT & 7) == 0 || nA < NOUT) {
                    float bv = __ldg(bias + nA);
                    float a0 = C[i][0] + bv, a2 = C[i][2] + bv;
                    if (RELU) { a0 = fmaxf(a0, 0.f); a2 = fmaxf(a2, 0.f); }
                    OUT[nA * 48 + m] = a0; OUT[nA * 48 + m + 8] = a2;
                }
                if ((NOUT & 7) == 0 || nB < NOUT) {
                    float bv = __ldg(bias + nB);
                    float a1 = C[i][1] + bv, a3 = C[i][3] + bv;
                    if (RELU) { a1 = fmaxf(a1, 0.f); a3 = fmaxf(a3, 0.f); }
                    OUT[nB * 48 + m] = a1; OUT[nB * 48 + m + 8] = a3;
                }
            }
        }
    }
}

// fused q,k,v: A fragments loaded once, 3 weight sets (KP=48, NOUT=36)
__device__ void tmmC3(const float* Sb,
                      const uint32_t* wh0, const uint32_t* wl0, const float* b0, float* O0,
                      const uint32_t* wh1, const uint32_t* wl1, const float* b1, float* O1,
                      const uint32_t* wh2, const uint32_t* wl2, const float* b2, float* O2,
                      int warp, int lane) {
    constexpr int NTN = 5, MYN = 2;
    const uint32_t* WH[3] = {wh0, wh1, wh2};
    const uint32_t* WL[3] = {wl0, wl1, wl2};
    const float*    BB[3] = {b0, b1, b2};
    float*          OO[3] = {O0, O1, O2};
    uint32_t sbase = (uint32_t)__cvta_generic_to_shared(Sb);
    int part = lane >> 3, rr = lane & 7;
    int g = lane >> 2, q2 = (lane & 3) * 2;
    #pragma unroll
    for (int mt = 0; mt < 3; mt++) {
        float C[3][MYN][4];
        #pragma unroll
        for (int mat = 0; mat < 3; mat++)
            #pragma unroll
            for (int i = 0; i < MYN; i++) { C[mat][i][0]=0.f; C[mat][i][1]=0.f; C[mat][i][2]=0.f; C[mat][i][3]=0.f; }
        #pragma unroll
        for (int kt = 0; kt < 3; kt++) {
            int m = mt * 16 + rr + (part & 1) * 8;
            int colb = (kt * 16 + ((part >> 1) << 3)) * 2;
            uint32_t off = (uint32_t)((m * 96 + colb) ^ swzm<48>(m));
            uint32_t ah0, ah1, ah2, ah3, al0, al1, al2, al3;
            ldm4(ah0, ah1, ah2, ah3, sbase + off);
            ldm4(al0, al1, al2, al3, sbase + 4608 + off);
            #pragma unroll
            for (int mat = 0; mat < 3; mat++) {
                #pragma unroll
                for (int i = 0; i < MYN; i++) {
                    int nt = warp + 4 * i;
                    if (nt < NTN) {
                        int pi = (nt * 8 + g) * 24 + kt * 8 + (lane & 3);
                        uint32_t bh0 = __ldg(WH[mat] + pi), bh1 = __ldg(WH[mat] + pi + 4);
                        uint32_t bl0 = __ldg(WL[mat] + pi), bl1 = __ldg(WL[mat] + pi + 4);
                        mma_bf16(C[mat][i][0], C[mat][i][1], C[mat][i][2], C[mat][i][3],
                                 ah0, ah1, ah2, ah3, bh0, bh1);
                        mma_bf16(C[mat][i][0], C[mat][i][1], C[mat][i][2], C[mat][i][3],
                                 ah0, ah1, ah2, ah3, bl0, bl1);
                        mma_bf16(C[mat][i][0], C[mat][i][1], C[mat][i][2], C[mat][i][3],
                                 al0, al1, al2, al3, bh0, bh1);
                    }
                }
            }
        }
        #pragma unroll
        for (int mat = 0; mat < 3; mat++) {
            #pragma unroll
            for (int i = 0; i < MYN; i++) {
                int nt = warp + 4 * i;
                if (nt < NTN) {
                    int m = mt * 16 + g;
                    int nA = nt * 8 + q2, nB = nA + 1;
                    if (nA < 36) {
                        float bv = __ldg(BB[mat] + nA);
                        OO[mat][nA * 48 + m] = C[mat][i][0] + bv;
                        OO[mat][nA * 48 + m + 8] = C[mat][i][2] + bv;
                    }
                    if (nB < 36) {
                        float bv = __ldg(BB[mat] + nB);
                        OO[mat][nB * 48 + m] = C[mat][i][1] + bv;
                        OO[mat][nB * 48 + m + 8] = C[mat][i][3] + bv;
                    }
                }
            }
        }
    }
}

// tin (KP=32, NOUT=36): epilogue adds bias+PE, writes h fp32 AND staged bf16 S.
__device__ void tmmC_tin(const float* Sb,
                         const uint32_t* __restrict__ wh, const uint32_t* __restrict__ wl,
                         const float* __restrict__ bias,
                         float* __restrict__ hout, float* __restrict__ Sst,
                         int warp, int lane) {
    constexpr int NTN = 5, MYN = 2;
    uint32_t sbase = (uint32_t)__cvta_generic_to_shared(Sb);
    uint32_t* SU = reinterpret_cast<uint32_t*>(Sst);
    int part = lane >> 3, rr = lane & 7;
    int g = lane >> 2, q2 = (lane & 3) * 2;
    uint32_t wr[MYN][2][4];
    #pragma unroll
    for (int i = 0; i < MYN; i++) {
        int nt = warp + 4 * i;
        #pragma unroll
        for (int kt = 0; kt < 2; kt++) {
            if (nt < NTN) {
                int pi = (nt * 8 + g) * 16 + kt * 8 + (lane & 3);
                wr[i][kt][0] = __ldg(wh + pi); wr[i][kt][1] = __ldg(wh + pi + 4);
                wr[i][kt][2] = __ldg(wl + pi); wr[i][kt][3] = __ldg(wl + pi + 4);
            } else {
                wr[i][kt][0] = wr[i][kt][1] = wr[i][kt][2] = wr[i][kt][3] = 0u;
            }
        }
    }
    #pragma unroll
    for (int mt = 0; mt < 3; mt++) {
        float C[MYN][4];
        #pragma unroll
        for (int i = 0; i < MYN; i++) { C[i][0]=0.f; C[i][1]=0.f; C[i][2]=0.f; C[i][3]=0.f; }
        #pragma unroll
        for (int kt = 0; kt < 2; kt++) {
            int m = mt * 16 + rr + (part & 1) * 8;
            int colb = (kt * 16 + ((part >> 1) << 3)) * 2;
            uint32_t off = (uint32_t)((m * 64 + colb) ^ swzm<32>(m));
            uint32_t ah0, ah1, ah2, ah3, al0, al1, al2, al3;
            ldm4(ah0, ah1, ah2, ah3, sbase + off);
            ldm4(al0, al1, al2, al3, sbase + 3072 + off);
            #pragma unroll
            for (int i = 0; i < MYN; i++) {
                int nt = warp + 4 * i;
                if (nt < NTN) {
                    mma_bf16(C[i][0], C[i][1], C[i][2], C[i][3], ah0, ah1, ah2, ah3, wr[i][kt][0], wr[i][kt][1]);
                    mma_bf16(C[i][0], C[i][1], C[i][2], C[i][3], ah0, ah1, ah2, ah3, wr[i][kt][2], wr[i][kt][3]);
                    mma_bf16(C[i][0], C[i][1], C[i][2], C[i][3], al0, al1, al2, al3, wr[i][kt][0], wr[i][kt][1]);
                }
            }
        }
        #pragma unroll
        for (int i = 0; i < MYN; i++) {
            int nt = warp + 4 * i;
            if (nt < NTN) {
                int m = mt * 16 + g;
                int nA = nt * 8 + q2, nB = nA + 1;
                if (nA < 36) {   // nA even; nA<36 implies nB<36
                    int t0 = m % Tn, t1 = (m + 8) % Tn;
                    float bA = __ldg(bias + nA), bB = __ldg(bias + nB);
                    float v0 = C[i][0] + bA + __ldg(d_pe + nA * Tn + t0);
                    float v1 = C[i][1] + bB + __ldg(d_pe + nB * Tn + t0);
                    float v2 = C[i][2] + bA + __ldg(d_pe + nA * Tn + t1);
                    float v3 = C[i][3] + bB + __ldg(d_pe + nB * Tn + t1);
                    hout[nA * 48 + m] = v0;     hout[nB * 48 + m] = v1;
                    hout[nA * 48 + m + 8] = v2; hout[nB * 48 + m + 8] = v3;
                    uint32_t hi, lo;
                    int p = nA >> 1;
                    bfpair(v0, v1, hi, lo);
                    int by0 = (m * 96 + p * 4) ^ swzm<48>(m);
                    SU[by0 >> 2] = hi; SU[1152 + (by0 >> 2)] = lo;
                    bfpair(v2, v3, hi, lo);
                    int by1 = ((m + 8) * 96 + p * 4) ^ swzm<48>(m + 8);
                    SU[by1 >> 2] = hi; SU[1152 + (by1 >> 2)] = lo;
                }
            }
        }
    }
}

// ffn1: staged-A (KP=48) -> OUT staged bf16 [48][144] hi/lo in U (relu)
__device__ void tmmB(const float* Sb,
                     const uint32_t* __restrict__ wh, const uint32_t* __restrict__ wl,
                     const float* __restrict__ bias, float* __restrict__ OUTf,
                     int warp, int lane) {
    constexpr int NTN = 18;
    constexpr int MYN = 5;
    uint32_t sbase = (uint32_t)__cvta_generic_to_shared(Sb);
    uint32_t* OU = reinterpret_cast<uint32_t*>(OUTf);
    int part = lane >> 3, rr = lane & 7;
    int g = lane >> 2, q2 = (lane & 3) * 2;
    #pragma unroll
    for (int mt = 0; mt < 3; mt++) {
        float C[MYN][4];
        #pragma unroll
        for (int i = 0; i < MYN; i++) { C[i][0]=0.f; C[i][1]=0.f; C[i][2]=0.f; C[i][3]=0.f; }
        #pragma unroll
        for (int kt = 0; kt < 3; kt++) {
            int m = mt * 16 + rr + (part & 1) * 8;
            int colb = (kt * 16 + ((part >> 1) << 3)) * 2;
            uint32_t off = (uint32_t)((m * 96 + colb) ^ swzm<48>(m));
            uint32_t ah0, ah1, ah2, ah3, al0, al1, al2, al3;
            ldm4(ah0, ah1, ah2, ah3, sbase + off);
            ldm4(al0, al1, al2, al3, sbase + 4608 + off);
            #pragma unroll
            for (int i = 0; i < MYN; i++) {
                int nt = warp + 4 * i;
                if (nt < NTN) {
                    int pi = (nt * 8 + g) * 24 + kt * 8 + (lane & 3);
                    uint32_t bh0 = __ldg(wh + pi), bh1 = __ldg(wh + pi + 4);
                    uint32_t bl0 = __ldg(wl + pi), bl1 = __ldg(wl + pi + 4);
                    mma_bf16(C[i][0], C[i][1], C[i][2], C[i][3], ah0, ah1, ah2, ah3, bh0, bh1);
                    mma_bf16(C[i][0], C[i][1], C[i][2], C[i][3], ah0, ah1, ah2, ah3, bl0, bl1);
                    mma_bf16(C[i][0], C[i][1], C[i][2], C[i][3], al0, al1, al2, al3, bh0, bh1);
                }
            }
        }
        #pragma unroll
        for (int i = 0; i < MYN; i++) {
            int nt = warp + 4 * i;
            if (nt < NTN) {
                int m = mt * 16 + g;
                int nA = nt * 8 + q2;
                float bv0 = __ldg(bias + nA), bv1 = __ldg(bias + nA + 1);
                float a0 = fmaxf(C[i][0] + bv0, 0.f), a1 = fmaxf(C[i][1] + bv1, 0.f);
                float a2 = fmaxf(C[i][2] + bv0, 0.f), a3 = fmaxf(C[i][3] + bv1, 0.f);
                int pidx = nt * 4 + (lane & 3);
                uint32_t hi, lo;
                bfpair(a0, a1, hi, lo);
                int b0 = (m * 288 + pidx * 4) ^ swzm<144>(m);
                OU[b0 >> 2] = hi; OU[3456 + (b0 >> 2)] = lo;
                bfpair(a2, a3, hi, lo);
                int b1 = ((m + 8) * 288 + pidx * 4) ^ swzm<144>(m + 8);
                OU[b1 >> 2] = hi; OU[3456 + (b1 >> 2)] = lo;
            }
        }
    }
}

// ---------------- scalar helpers ----------------------------------------------
__device__ __forceinline__ uint64_t pack2(float v) {
    uint64_t r;
    asm("mov.b64 %0, {%1, %1};" : "=l"(r) : "f"(v));
    return r;
}
__device__ __forceinline__ void fma2(uint64_t& acc, uint64_t a, uint64_t b) {
    asm("fma.rn.f32x2 %0, %1, %2, %0;" : "+l"(acc) : "l"(a), "l"(b));
}
__device__ __forceinline__ float2 unpack2(uint64_t v) {
    float lo, hi;
    asm("mov.b64 {%0, %1}, %2;" : "=f"(lo), "=f"(hi) : "l"(v));
    return make_float2(lo, hi);
}

// LN + staged emit, ALIAS-SAFE (internal barrier in uniform control flow)
__device__ __forceinline__ void layernorm2s(float* __restrict__ h,
                                            const float* __restrict__ res,
                                            const float* __restrict__ g,
                                            const float* __restrict__ bb,
                                            float* __restrict__ Sst, int tid) {
    uint32_t* SU = reinterpret_cast<uint32_t*>(Sst);
    int r = tid >> 1, half = tid & 1;
    float vloc[18];
    float m = 0.0f, rs = 0.0f;
    if (tid < 96) {
        float q2 = 0.0f;
        #pragma unroll
        for (int kk = 0; kk < 18; kk++) {
            int k = half * 18 + kk;
            float v = h[k * Rn + r] + res[k * Rn + r];
            vloc[kk] = v;
            m += v; q2 += v * v;
        }
        m  += __shfl_xor_sync(0xffffffffu, m, 1);
        q2 += __shfl_xor_sync(0xffffffffu, q2, 1);
        m *= (1.0f / HIDn);
        float var = q2 * (1.0f / HIDn) - m * m;
        rs = rsqrtf(var + 1e-5f);
    }
    __syncthreads();
    if (tid < 96) {
        #pragma unroll
        for (int i = 0; i < 9; i++) {
            int k = half * 18 + 2 * i;
            float v0 = (vloc[2 * i]     - m) * rs * __ldg(g + k)     + __ldg(bb + k);
            float v1 = (vloc[2 * i + 1] - m) * rs * __ldg(g + k + 1) + __ldg(bb + k + 1);
            h[k * Rn + r] = v0;
            h[(k + 1) * Rn + r] = v1;
            uint32_t hi, lo;
            bfpair(v0, v1, hi, lo);
            int p = half * 9 + i;
            int byte = (r * 96 + p * 4) ^ swzm<48>(r);
            SU[byte >> 2] = hi; SU[1152 + (byte >> 2)] = lo;
        }
    }
    for (int u = tid; u < 288; u += NT) {
        int rr2 = u % 48, p = 18 + u / 48;
        int byte = (rr2 * 96 + p * 4) ^ swzm<48>(rr2);
        SU[byte >> 2] = 0; SU[1152 + (byte >> 2)] = 0;
    }
}

// ---------------- K6: mega-kernel ---------------------------------------------
__global__ __launch_bounds__(NT, 5)
void k_mega(const float* __restrict__ W0,  const float* __restrict__ W1,
            const float* __restrict__ cb,  const float* __restrict__ tinb,
            const float* __restrict__ bq,  const float* __restrict__ bk,
            const float* __restrict__ bv,  const float* __restrict__ bo,
            const float* __restrict__ g1,  const float* __restrict__ b1,
            const float* __restrict__ fb1, const float* __restrict__ fb2,
            const float* __restrict__ g2,  const float* __restrict__ b2,
            const float* __restrict__ fcW, const float* __restrict__ fcb,
            float* __restrict__ out) {
    __shared__ __align__(16) float sh_h[HIDn * Rn];     // 1728
    __shared__ __align__(16) float sh_U[FFNn * Rn];     // 6912 (27648 B)
    __shared__ __align__(16) float sh_S[2304];          // 9216 B

    float* h = sh_h;
    float* U = sh_U;
    float* S = sh_S;
    float* x   = U;
    float* tx  = U + 672;
    float* cat = U + 1344;

    const int tid = threadIdx.x;
    const int warp = tid >> 5, lane = tid & 31;
    const int nbase = blockIdx.x * SEQ;

    // ---- stage self tiles ----
    for (int idx = tid; idx < SEQ * Tn * INF; idx += NT) {
        int s2 = idx / 336, u = idx % 336;
        int t = u / INF, f = u % INF;
        int n2 = nbase + s2;
        x  [f * Rn + s2 * Tn + t] = d_xn [n2 * 336 + u];
        cat[f * Rn + s2 * Tn + t] = d_xn2[n2 * 336 + u];
    }

    // ---- ChebConv gather ----
    {
        int s2 = tid >> 6, l = tid & 63;
        int n2 = nbase + s2;
        int b = n2 >> 9, c = n2 & (Cn - 1);
        float acc[6];
        #pragma unroll
        for (int i = 0; i < 6; i++) acc[i] = 0.0f;
        int start = d_off[c], end = d_off[c + 1];
        for (int e = start; e < end; e++) {
            int   rr = __ldg(d_brow + e);
            float w  = __ldg(d_bw + e);
            const float* nb = d_xn + (b * Cn + rr) * 336;
            #pragma unroll
            for (int i = 0; i < 6; i++) {
                int u = l + i * 64;
                if (u < 336) acc[i] = fmaf(w, nb[u], acc[i]);
            }
        }
        #pragma unroll
        for (int i = 0; i < 6; i++) {
            int u = l + i * 64;
            if (u < 336) {
                int t = u / INF, f = u % INF;
                tx[f * Rn + s2 * Tn + t] = acc[i];
            }
        }
    }
    __syncthreads();

    // ---- gate ----
    for (int idx = tid; idx < Rn * INF; idx += NT) {
        int r = idx % Rn, j = idx / Rn;
        float sacc = __ldg(cb + j);
        #pragma unroll
        for (int f = 0; f < INF; f++) {
            sacc = fmaf(x [f * Rn + r], __ldg(W0 + f * INF + j), sacc);
            sacc = fmaf(tx[f * Rn + r], __ldg(W1 + f * INF + j), sacc);
        }
        cat[(INF + j) * Rn + r] = __fdividef(1.0f, 1.0f + __expf(-sacc));
    }
    __syncthreads();

    // ---- tin (tensor): staged input in dead U space; epilogue emits h+PE+staged S ----
    stageA<32, 28>(cat, U + 4608, tid);
    __syncthreads();
    tmmC_tin(U + 4608, d_wbh, d_wbl, tinb, h, S, warp, lane);
    // zero S pads (pairs 18..23)
    {
        uint32_t* SU = reinterpret_cast<uint32_t*>(S);
        for (int u = tid; u < 288; u += NT) {
            int r = u % 48, p = 18 + u / 48;
            int byte = (r * 96 + p * 4) ^ swzm<48>(r);
            SU[byte >> 2] = 0; SU[1152 + (byte >> 2)] = 0;
        }
    }
    __syncthreads();

    const float scale = 0.23570226039551584f;
    #pragma unroll 1
    for (int l = 0; l < 2; l++) {
        const uint32_t* wqh = d_wbh + OFF_QKVO + (l * 4 + 0) * 960;
        const uint32_t* wkh = d_wbh + OFF_QKVO + (l * 4 + 1) * 960;
        const uint32_t* wvh = d_wbh + OFF_QKVO + (l * 4 + 2) * 960;
        const uint32_t* woh = d_wbh + OFF_QKVO + (l * 4 + 3) * 960;
        const uint32_t* wql = d_wbl + OFF_QKVO + (l * 4 + 0) * 960;
        const uint32_t* wkl = d_wbl + OFF_QKVO + (l * 4 + 1) * 960;
        const uint32_t* wvl = d_wbl + OFF_QKVO + (l * 4 + 2) * 960;
        const uint32_t* wol = d_wbl + OFF_QKVO + (l * 4 + 3) * 960;
        const uint32_t* f1h = d_wbh + OFF_F1 + l * 3456;
        const uint32_t* f1l = d_wbl + OFF_F1 + l * 3456;
        const uint32_t* f2h = d_wbh + OFF_F2 + l * 2880;
        const uint32_t* f2l = d_wbl + OFF_F2 + l * 2880;
        const float* bq_l = bq + l * HIDn;  const float* bk_l = bk + l * HIDn;
        const float* bv_l = bv + l * HIDn;  const float* bo_l = bo + l * HIDn;
        const float* g1_l = g1 + l * HIDn;  const float* b1_l = b1 + l * HIDn;
        const float* g2_l = g2 + l * HIDn;  const float* b2_l = b2 + l * HIDn;
        const float* fb1_l = fb1 + l * FFNn; const float* fb2_l = fb2 + l * HIDn;

        // ---- q,k,v fused (A fragments loaded once) ----
        tmmC3(S, wqh, wql, bq_l, U,
                 wkh, wkl, bk_l, U + 1728,
                 wvh, wvl, bv_l, U + 3456, warp, lane);
        __syncthreads();

        // ---- scores (overwrite S) ----
        for (int tile = tid; tile < 144; tile += NT) {
            int bs = tile / 36, rem = tile % 36;
            int ig = rem % 6, jg = rem / 6;
            int s2 = bs >> 1, hh = bs & 1;
            const float* qb = U        + hh * HDn * Rn + s2 * Tn + ig * 4;
            const float* kb = U + 1728 + hh * HDn * Rn + s2 * Tn + jg * 4;
            uint64_t acc[8];
            #pragma unroll
            for (int i = 0; i < 8; i++) acc[i] = 0ull;
            #pragma unroll 2
            for (int d = 0; d < HDn; d++) {
                ulonglong2 qv = *(const ulonglong2*)(qb + d * Rn);
                float4 kv = *(const float4*)(kb + d * Rn);
                uint64_t k0 = pack2(kv.x), k1 = pack2(kv.y), k2 = pack2(kv.z), k3 = pack2(kv.w);
                fma2(acc[0], qv.x, k0); fma2(acc[1], qv.y, k0);
                fma2(acc[2], qv.x, k1); fma2(acc[3], qv.y, k1);
                fma2(acc[4], qv.x, k2); fma2(acc[5], qv.y, k2);
                fma2(acc[6], qv.x, k3); fma2(acc[7], qv.y, k3);
            }
            int rowbase = s2 * 48 + hh * 24 + ig * 4;
            #pragma unroll
            for (int jj = 0; jj < 4; jj++) {
                float2 lo = unpack2(acc[2 * jj]);
                float2 hi = unpack2(acc[2 * jj + 1]);
                *(float4*)(S + (jg * 4 + jj) * 96 + rowbase) =
                    make_float4(lo.x * scale, lo.y * scale, hi.x * scale, hi.y * scale);
            }
        }
        __syncthreads();

        // softmax
        if (tid < 96) {
            float m = S[tid];
            #pragma unroll
            for (int j = 1; j < Tn; j++) m = fmaxf(m, S[j * 96 + tid]);
            float sum = 0.0f;
            #pragma unroll
            for (int j = 0; j < Tn; j++) {
                float e = __expf(S[j * 96 + tid] - m);
                S[j * 96 + tid] = e;
                sum += e;
            }
            float inv = __fdividef(1.0f, sum);
            #pragma unroll
            for (int j = 0; j < Tn; j++) S[j * 96 + tid] *= inv;
        }
        __syncthreads();

        // ---- attn out: staged bf16 [48][48] into U[0..2304) (q/k space, dead) ----
        {
            uint32_t* UU = reinterpret_cast<uint32_t*>(U);
            for (int tile = tid; tile < 216; tile += NT) {
                int s2 = tile / 108, rem = tile % 108;
                int og = rem / 6, tg = rem % 6;
                int o0 = og * 2, hh = o0 / HDn;
                const float* ab = S + s2 * 48 + hh * 24 + tg * 4;
                const float* vb = U + 3456 + o0 * Rn + s2 * Tn;
                uint64_t acc[4];
                #pragma unroll
                for (int i = 0; i < 4; i++) acc[i] = 0ull;
                #pragma unroll 4
                for (int j = 0; j < Tn; j++) {
                    ulonglong2 avv = *(const ulonglong2*)(ab + j * 96);
                    uint64_t p0 = pack2(vb[j]);
                    uint64_t p1 = pack2(vb[Rn + j]);
                    fma2(acc[0], avv.x, p0); fma2(acc[1], avv.y, p0);
                    fma2(acc[2], avv.x, p1); fma2(acc[3], avv.y, p1);
                }
                float2 a0 = unpack2(acc[0]), a1 = unpack2(acc[1]);
                float2 a2 = unpack2(acc[2]), a3 = unpack2(acc[3]);
                float v0s[4] = {a0.x, a0.y, a1.x, a1.y};
                float v1s[4] = {a2.x, a2.y, a3.x, a3.y};
                #pragma unroll
                for (int rr = 0; rr < 4; rr++) {
                    int m = s2 * Tn + tg * 4 + rr;
                    uint32_t hi, lo;
                    bfpair(v0s[rr], v1s[rr], hi, lo);
                    int byte = (m * 96 + og * 4) ^ swzm<48>(m);
                    UU[byte >> 2] = hi; UU[1152 + (byte >> 2)] = lo;
                }
            }
            for (int u = tid; u < 288; u += NT) {
                int r = u % 48, p = 18 + u / 48;
                int byte = (r * 96 + p * 4) ^ swzm<48>(r);
                UU[byte >> 2] = 0; UU[1152 + (byte >> 2)] = 0;
            }
        }
        __syncthreads();

        // ---- Wo (tensor, hoisted weights): staged U -> fp32 U+5184 ----
        tmmC<48, HIDn, false, true>(U, woh, wol, bo_l, U + 5184, warp, lane);
        __syncthreads();

        // ---- LN1 -> h fp32 + staged S ----
        layernorm2s(h, U + 5184, g1_l, b1_l, S, tid);
        __syncthreads();

        // ---- ffn1: staged S -> staged bf16 U (relu) ----
        tmmB(S, f1h, f1l, fb1_l, U, warp, lane);
        __syncthreads();

        // ---- ffn2: staged U (KP=144) -> fp32 S ----
        tmmC<144, HIDn, false, false>(U, f2h, f2l, fb2_l, S, warp, lane);
        __syncthreads();

        // ---- LN2 -> h fp32 + staged S (alias handled inside) ----
        layernorm2s(h, S, g2_l, b2_l, S, tid);
        __syncthreads();
    }

    // ---- fc + store ----
    if (tid < Rn) {
        int r = tid;
        int s2 = r / Tn, t = r % Tn;
        int n2 = nbase + s2;
        int b = n2 >> 9, c = n2 & (Cn - 1);
        float acc = __ldg(fcb);
        #pragma unroll
        for (int k = 0; k < HIDn; k++) acc = fmaf(h[k * Rn + r], __ldg(fcW + k), acc);
        out[(b * Tn + t) * Cn + c] = acc;
    }
}

// ---------------- launch ------------------------------------------------------
extern "C" void kernel_launch(void* const* d_in, const int* in_sizes, int n_in,
                              void* d_out, int out_size) {
    const float *pm, *ft, *W0, *W1, *cb, *tinW, *tinb, *Wq, *bq, *Wk, *bk,
                *Wv, *bv, *Wo, *bo, *g1, *b1, *fW1, *fb1, *fW2, *fb2,
                *g2, *b2, *fcW, *fcb;
    const int* ei;

    if (in_sizes[2] == 2 * EG) {
        pm  = (const float*)d_in[0];  ft  = (const float*)d_in[1];
        ei  = (const int*)  d_in[2];
        W0  = (const float*)d_in[3];  W1  = (const float*)d_in[4];
        cb  = (const float*)d_in[5];
        tinW= (const float*)d_in[6];  tinb= (const float*)d_in[7];
        Wq  = (const float*)d_in[8];  bq  = (const float*)d_in[9];
        Wk  = (const float*)d_in[10]; bk  = (const float*)d_in[11];
        Wv  = (const float*)d_in[12]; bv  = (const float*)d_in[13];
        Wo  = (const float*)d_in[14]; bo  = (const float*)d_in[15];
        g1  = (const float*)d_in[16]; b1  = (const float*)d_in[17];
        fW1 = (const float*)d_in[18]; fb1 = (const float*)d_in[19];
        fW2 = (const float*)d_in[20]; fb2 = (const float*)d_in[21];
        g2  = (const float*)d_in[22]; b2  = (const float*)d_in[23];
        fcW = (const float*)d_in[24]; fcb = (const float*)d_in[25];
    } else {
        pm  = (const float*)d_in[0];  ft  = (const float*)d_in[1];
        W0  = (const float*)d_in[2];  W1  = (const float*)d_in[3];
        cb  = (const float*)d_in[4];
        tinW= (const float*)d_in[5];  tinb= (const float*)d_in[6];
        Wq  = (const float*)d_in[7];  bq  = (const float*)d_in[8];
        Wk  = (const float*)d_in[9];  bk  = (const float*)d_in[10];
        Wv  = (const float*)d_in[11]; bv  = (const float*)d_in[12];
        Wo  = (const float*)d_in[13]; bo  = (const float*)d_in[14];
        g1  = (const float*)d_in[15]; b1  = (const float*)d_in[16];
        fW1 = (const float*)d_in[17]; fb1 = (const float*)d_in[18];
        fW2 = (const float*)d_in[19]; fb2 = (const float*)d_in[20];
        g2  = (const float*)d_in[21]; b2  = (const float*)d_in[22];
        fcW = (const float*)d_in[23]; fcb = (const float*)d_in[24];
        ei  = (const int*)  d_in[25];
    }

    k_count<<<Cn, 32>>>(ei);
    k_scan <<<1, Cn>>>();
    k_fill <<<Cn, 32>>>(ei);
    {
        int total = Nn * Tn * INF;
        k_pack<<<(total + 255) / 256, 256>>>(pm, ft);
    }
    k_wprep<<<(WB_TOT + 255) / 256, 256>>>(tinW, Wq, Wk, Wv, Wo, fW1, fW2);
    k_mega<<<Nn / SEQ, NT>>>(W0, W1, cb, tinb,
                             bq, bk, bv, bo, g1, b1, fb1, fb2, g2, b2,
                             fcW, fcb, (float*)d_out);
}